// round 2
// baseline (speedup 1.0000x reference)
#include <cuda_runtime.h>
#include <math.h>

#define B_  2
#define H_  2048
#define L_  4096
#define LK  128
#define LAM 0.003f

// Scratch: gelu(conv(u)+D*u), layout [B, H, L]
__device__ float g_y[(size_t)B_ * H_ * L_];

// ---------------------------------------------------------------------------
// Kernel 1: soft-threshold FIR conv (128 taps, causal) + D skip + exact GELU
// One block per (b,h) row. 128 threads, each thread computes 8 outputs per
// 1024-wide tile using a rolling register window (1 LDS per 8 FMAs).
// ---------------------------------------------------------------------------
__global__ __launch_bounds__(128) void conv_gelu_kernel(
    const float* __restrict__ u,
    const float* __restrict__ kern,
    const float* __restrict__ D)
{
    const int bh  = blockIdx.x;
    const int b   = bh / H_;
    const int h   = bh % H_;
    const int tid = threadIdx.x;

    __shared__ float ks[LK];
    __shared__ float us[1152];   // 128 halo + 1024 tile

    if (tid < LK) {
        float kv = kern[h * LK + tid];
        float a  = fabsf(kv) - LAM;
        a = a > 0.f ? a : 0.f;
        ks[tid] = (kv > 0.f) ? a : ((kv < 0.f) ? -a : 0.f);
    }
    const float Dh = D[h];
    const float* urow = u   + ((size_t)b * H_ + h) * L_;
    float*       yrow = g_y + ((size_t)b * H_ + h) * L_;

    for (int t = 0; t < 4; t++) {
        const int l0 = t * 1024;
        __syncthreads();
        for (int i = tid; i < 1152; i += 128) {
            int gl = l0 - 128 + i;
            us[i] = (gl >= 0) ? urow[gl] : 0.f;
        }
        __syncthreads();

        const int o = tid * 8;   // local output base within tile
        float uw[8];
        #pragma unroll
        for (int m = 0; m < 8; m++) uw[m] = us[o + 128 + m];  // window for j=0

        float acc[8] = {0.f,0.f,0.f,0.f,0.f,0.f,0.f,0.f};

        #pragma unroll 8
        for (int j = 0; j < LK; j++) {
            const float kj = ks[j];
            #pragma unroll
            for (int m = 0; m < 8; m++) acc[m] = fmaf(kj, uw[m], acc[m]);
            // slide window down by one input element
            #pragma unroll
            for (int m = 7; m > 0; m--) uw[m] = uw[m - 1];
            uw[0] = us[o + 127 - j];   // valid down to us[o] at j=127
        }

        #pragma unroll
        for (int m = 0; m < 8; m++) {
            float x  = acc[m] + Dh * us[o + 128 + m];
            float gv = 0.5f * x * (1.f + erff(x * 0.70710678118654752f));
            yrow[l0 + o + m] = gv;
        }
    }
}

// ---------------------------------------------------------------------------
// Kernel 2: Z = W[2H,H] x Y[H, L] per batch, fused GLU epilogue.
// Each CTA computes a 128(h) x 64(l) tile of BOTH the 'a' rows (h) and the
// 'g' rows (h+H), sharing the Y tile load. BK=16, 256 threads, 8x4 dual
// micro-tile per thread. Double-buffered smem: global prefetch into regs
// overlaps FMAs; one __syncthreads() per K-slice.
// ---------------------------------------------------------------------------
#define BM 128
#define BN 64
#define BK 16
#define NK (H_ / BK)

__global__ __launch_bounds__(256) void gemm_glu_kernel(
    const float* __restrict__ W,
    const float* __restrict__ bias,
    float* __restrict__ out)
{
    const int l0  = blockIdx.x * BN;
    const int h0  = blockIdx.y * BM;
    const int b   = blockIdx.z;
    const int tid = threadIdx.x;

    __shared__ float Aa[2][BK][BM];
    __shared__ float Ag[2][BK][BM];
    __shared__ float Bs[2][BK][BN];

    const float* Y = g_y + (size_t)b * H_ * L_;

    // Per-thread load coordinates (fixed across iterations)
    const int wr0 = tid >> 2;                // 0..63   W row (first half)
    const int wr1 = (tid + 256) >> 2;        // 64..127 W row (second half)
    const int wc  = (tid & 3) * 4;           // 0,4,8,12
    const int br  = tid >> 4;                // 0..15  Y row
    const int bc  = (tid & 15) * 4;          // 0..60  Y col

    const float* pWa0 = &W[(size_t)(h0 + wr0)      * H_ + wc];
    const float* pWa1 = &W[(size_t)(h0 + wr1)      * H_ + wc];
    const float* pWg0 = &W[(size_t)(h0 + wr0 + H_) * H_ + wc];
    const float* pWg1 = &W[(size_t)(h0 + wr1 + H_) * H_ + wc];
    const float* pY   = &Y[(size_t)br * L_ + l0 + bc];

    float acc_a[8][4];
    float acc_g[8][4];
    #pragma unroll
    for (int m = 0; m < 8; m++)
        #pragma unroll
        for (int q = 0; q < 4; q++) { acc_a[m][q] = 0.f; acc_g[m][q] = 0.f; }

    const int ty = tid / 16;   // 0..15 -> row group ty*8
    const int tx = tid % 16;   // 0..15 -> col group tx*4

    // ---- load stage 0 ----
    {
        float4 va0 = *(const float4*)(pWa0);
        float4 va1 = *(const float4*)(pWa1);
        float4 vg0 = *(const float4*)(pWg0);
        float4 vg1 = *(const float4*)(pWg1);
        float4 vb  = *(const float4*)(pY);
        Aa[0][wc+0][wr0]=va0.x; Aa[0][wc+1][wr0]=va0.y; Aa[0][wc+2][wr0]=va0.z; Aa[0][wc+3][wr0]=va0.w;
        Aa[0][wc+0][wr1]=va1.x; Aa[0][wc+1][wr1]=va1.y; Aa[0][wc+2][wr1]=va1.z; Aa[0][wc+3][wr1]=va1.w;
        Ag[0][wc+0][wr0]=vg0.x; Ag[0][wc+1][wr0]=vg0.y; Ag[0][wc+2][wr0]=vg0.z; Ag[0][wc+3][wr0]=vg0.w;
        Ag[0][wc+0][wr1]=vg1.x; Ag[0][wc+1][wr1]=vg1.y; Ag[0][wc+2][wr1]=vg1.z; Ag[0][wc+3][wr1]=vg1.w;
        *(float4*)&Bs[0][br][bc] = vb;
    }
    __syncthreads();

    int s = 0;
    for (int k = 0; k < NK; k++) {
        // ---- prefetch next slice into registers ----
        float4 va0, va1, vg0, vg1, vb;
        const bool more = (k + 1 < NK);
        if (more) {
            const int koff = (k + 1) * BK;
            va0 = *(const float4*)(pWa0 + koff);
            va1 = *(const float4*)(pWa1 + koff);
            vg0 = *(const float4*)(pWg0 + koff);
            vg1 = *(const float4*)(pWg1 + koff);
            vb  = *(const float4*)(pY + (size_t)koff * L_);
        }

        // ---- compute on current stage ----
        #pragma unroll
        for (int kk = 0; kk < BK; kk++) {
            float4 b0 = *(const float4*)&Bs[s][kk][tx * 4];
            float4 a0 = *(const float4*)&Aa[s][kk][ty * 8];
            float4 a1 = *(const float4*)&Aa[s][kk][ty * 8 + 4];
            float4 g0 = *(const float4*)&Ag[s][kk][ty * 8];
            float4 g1 = *(const float4*)&Ag[s][kk][ty * 8 + 4];
            float av[8] = {a0.x,a0.y,a0.z,a0.w,a1.x,a1.y,a1.z,a1.w};
            float gv[8] = {g0.x,g0.y,g0.z,g0.w,g1.x,g1.y,g1.z,g1.w};
            float bv[4] = {b0.x,b0.y,b0.z,b0.w};
            #pragma unroll
            for (int m = 0; m < 8; m++)
                #pragma unroll
                for (int q = 0; q < 4; q++) {
                    acc_a[m][q] = fmaf(av[m], bv[q], acc_a[m][q]);
                    acc_g[m][q] = fmaf(gv[m], bv[q], acc_g[m][q]);
                }
        }

        // ---- store prefetched regs to the other stage ----
        if (more) {
            const int d = s ^ 1;
            Aa[d][wc+0][wr0]=va0.x; Aa[d][wc+1][wr0]=va0.y; Aa[d][wc+2][wr0]=va0.z; Aa[d][wc+3][wr0]=va0.w;
            Aa[d][wc+0][wr1]=va1.x; Aa[d][wc+1][wr1]=va1.y; Aa[d][wc+2][wr1]=va1.z; Aa[d][wc+3][wr1]=va1.w;
            Ag[d][wc+0][wr0]=vg0.x; Ag[d][wc+1][wr0]=vg0.y; Ag[d][wc+2][wr0]=vg0.z; Ag[d][wc+3][wr0]=vg0.w;
            Ag[d][wc+0][wr1]=vg1.x; Ag[d][wc+1][wr1]=vg1.y; Ag[d][wc+2][wr1]=vg1.z; Ag[d][wc+3][wr1]=vg1.w;
            *(float4*)&Bs[d][br][bc] = vb;
            __syncthreads();
            s = d;
        }
    }

    // Epilogue: bias + GLU (a * sigmoid(g)), vectorized stores
    #pragma unroll
    for (int m = 0; m < 8; m++) {
        const int h  = h0 + ty * 8 + m;
        const float ba = bias[h];
        const float bg = bias[h + H_];
        float res[4];
        #pragma unroll
        for (int q = 0; q < 4; q++) {
            float za = acc_a[m][q] + ba;
            float zg = acc_g[m][q] + bg;
            res[q] = za / (1.f + expf(-zg));
        }
        float* orow = out + ((size_t)b * H_ + h) * L_ + l0 + tx * 4;
        *(float4*)orow = make_float4(res[0], res[1], res[2], res[3]);
    }
}

// ---------------------------------------------------------------------------
extern "C" void kernel_launch(void* const* d_in, const int* in_sizes, int n_in,
                              void* d_out, int out_size)
{
    const float* u    = (const float*)d_in[0];   // [B,H,L]
    const float* kern = (const float*)d_in[1];   // [1,H,128]
    const float* D    = (const float*)d_in[2];   // [1,H]
    const float* W    = (const float*)d_in[3];   // [2H,H]
    const float* bias = (const float*)d_in[4];   // [2H]
    float* out = (float*)d_out;                  // [B,H,L]

    conv_gelu_kernel<<<B_ * H_, 128>>>(u, kern, D);

    dim3 grid(L_ / BN, H_ / BM, B_);
    gemm_glu_kernel<<<grid, 256>>>(W, bias, out);
}

// round 4
// speedup vs baseline: 2.3628x; 2.3628x over previous
#include <cuda_runtime.h>
#include <cstdint>
#include <math.h>

#define B_  2
#define H_  2048
#define L_  4096
#define LK  128
#define LAM 0.003f

// Scratch: gelu(conv(u)+D*u), layout [B, H, L]  (== B operand [k][n] layout)
__device__ float g_y[(size_t)B_ * H_ * L_];

// ============================================================================
// Helpers
// ============================================================================
__device__ __forceinline__ uint32_t smem_to_u32(const void* p) {
    uint32_t a;
    asm("{ .reg .u64 t; cvta.to.shared.u64 t, %1; cvt.u32.u64 %0, t; }"
        : "=r"(a) : "l"(p));
    return a;
}
__device__ __forceinline__ uint32_t f2tf32(float x) {
    uint32_t r;
    asm("cvt.rna.tf32.f32 %0, %1;" : "=r"(r) : "f"(x));
    return r;
}
__device__ __forceinline__ void cp16(uint32_t dst, const void* src) {
    asm volatile("cp.async.cg.shared.global [%0], [%1], 16;"
                 :: "r"(dst), "l"(src));
}
#define CP_COMMIT() asm volatile("cp.async.commit_group;" ::: "memory")
#define CP_WAIT(N)  asm volatile("cp.async.wait_group %0;" :: "n"(N) : "memory")

__device__ __forceinline__ void mma_tf32(float* c, const uint32_t* a, const uint32_t* b) {
    asm volatile(
        "mma.sync.aligned.m16n8k8.row.col.f32.tf32.tf32.f32 "
        "{%0,%1,%2,%3}, {%4,%5,%6,%7}, {%8,%9}, {%0,%1,%2,%3};"
        : "+f"(c[0]), "+f"(c[1]), "+f"(c[2]), "+f"(c[3])
        : "r"(a[0]), "r"(a[1]), "r"(a[2]), "r"(a[3]), "r"(b[0]), "r"(b[1]));
}

// ============================================================================
// Kernel 1: 128-tap causal FIR conv + D skip + exact GELU (proven, unchanged)
// ============================================================================
__global__ __launch_bounds__(128) void conv_gelu_kernel(
    const float* __restrict__ u,
    const float* __restrict__ kern,
    const float* __restrict__ D)
{
    const int bh  = blockIdx.x;
    const int b   = bh / H_;
    const int h   = bh % H_;
    const int tid = threadIdx.x;

    __shared__ float ks[LK];
    __shared__ float us[1152];

    if (tid < LK) {
        float kv = kern[h * LK + tid];
        float a  = fabsf(kv) - LAM;
        a = a > 0.f ? a : 0.f;
        ks[tid] = (kv > 0.f) ? a : ((kv < 0.f) ? -a : 0.f);
    }
    const float Dh = D[h];
    const float* urow = u   + ((size_t)b * H_ + h) * L_;
    float*       yrow = g_y + ((size_t)b * H_ + h) * L_;

    for (int t = 0; t < 4; t++) {
        const int l0 = t * 1024;
        __syncthreads();
        for (int i = tid; i < 1152; i += 128) {
            int gl = l0 - 128 + i;
            us[i] = (gl >= 0) ? urow[gl] : 0.f;
        }
        __syncthreads();

        const int o = tid * 8;
        float uw[8];
        #pragma unroll
        for (int m = 0; m < 8; m++) uw[m] = us[o + 128 + m];

        float acc[8] = {0.f,0.f,0.f,0.f,0.f,0.f,0.f,0.f};

        #pragma unroll 8
        for (int j = 0; j < LK; j++) {
            const float kj = ks[j];
            #pragma unroll
            for (int m = 0; m < 8; m++) acc[m] = fmaf(kj, uw[m], acc[m]);
            #pragma unroll
            for (int m = 7; m > 0; m--) uw[m] = uw[m - 1];
            uw[0] = us[o + 127 - j];
        }

        #pragma unroll
        for (int m = 0; m < 8; m++) {
            float x  = acc[m] + Dh * us[o + 128 + m];
            yrow[l0 + o + m] = 0.5f * x * (1.f + erff(x * 0.70710678118654752f));
        }
    }
}

// ============================================================================
// Kernel 2: tf32 mma.sync GEMM + fused GLU.
// CTA: 128(h) x 64(l), both gates. BK=32 chunks, cp.async double-buffered.
// 8 warps in 4(M) x 2(N); warp tile 32x32 per gate.
// Smem strides: A rows 36 floats, B rows 72 floats (conflict-free frags).
// ============================================================================
#define BK       32
#define NKC      (H_ / BK)          // 64
#define A_STR    36
#define B_STR    72
#define OFF_AA   0
#define OFF_AG   (128 * A_STR)          // 4608 floats
#define OFF_B    (2 * 128 * A_STR)      // 9216 floats
#define STAGE_F  (2 * 128 * A_STR + 32 * B_STR)   // 11520 floats
#define SMEM_BYTES (2 * STAGE_F * 4)    // 92160 B

__global__ __launch_bounds__(256, 1) void gemm_glu_tc(
    const float* __restrict__ W,
    const float* __restrict__ bias,
    float* __restrict__ out)
{
    extern __shared__ float smem_f[];
    const uint32_t smem_u = smem_to_u32(smem_f);

    const int tid  = threadIdx.x;
    const int wid  = tid >> 5;
    const int lane = tid & 31;
    const int l0   = blockIdx.x * 64;
    const int h0   = blockIdx.y * 128;
    const int b    = blockIdx.z;

    const float* Y = g_y + (size_t)b * H_ * L_;

    // per-thread load coordinates
    const int ar = tid >> 3;             // 0..31  A row step (4 iters of +32... see loop)
    const int ac = (tid & 7) * 4;        // 0,4,...28
    const int br = tid >> 4;             // 0..15  B row (2 iters of +16)
    const int bc = (tid & 15) * 4;       // 0..60

    // issue one chunk's cp.async loads into stage s
    auto issue = [&](int k0, int s) {
        uint32_t sb = smem_u + (uint32_t)(s * STAGE_F) * 4u;
        #pragma unroll
        for (int i = 0; i < 4; i++) {
            int r = ar + i * 32;
            cp16(sb + (uint32_t)(OFF_AA + r * A_STR + ac) * 4u,
                 &W[(size_t)(h0 + r) * H_ + k0 + ac]);
            cp16(sb + (uint32_t)(OFF_AG + r * A_STR + ac) * 4u,
                 &W[(size_t)(h0 + r + H_) * H_ + k0 + ac]);
        }
        #pragma unroll
        for (int i = 0; i < 2; i++) {
            int r = br + i * 16;
            cp16(sb + (uint32_t)(OFF_B + r * B_STR + bc) * 4u,
                 &Y[(size_t)(k0 + r) * L_ + l0 + bc]);
        }
    };

    float acc_a[2][4][4];
    float acc_g[2][4][4];
    #pragma unroll
    for (int mt = 0; mt < 2; mt++)
        #pragma unroll
        for (int nt = 0; nt < 4; nt++)
            #pragma unroll
            for (int q = 0; q < 4; q++) { acc_a[mt][nt][q] = 0.f; acc_g[mt][nt][q] = 0.f; }

    // warp tile position
    const int wm = (wid & 3) * 32;       // M offset within 128
    const int wn = (wid >> 2) * 32;      // N offset within 64
    const int row = lane >> 2;           // 0..7
    const int col = lane & 3;            // 0..3

    issue(0, 0);
    CP_COMMIT();

    for (int kc = 0; kc < NKC; kc++) {
        if (kc + 1 < NKC) {
            issue((kc + 1) * BK, (kc + 1) & 1);
            CP_COMMIT();
            CP_WAIT(1);     // chunk kc resident; kc+1 in flight
        } else {
            CP_WAIT(0);
        }
        __syncthreads();

        const float* st = smem_f + (kc & 1) * STAGE_F;
        const float* pa = st + OFF_AA;
        const float* pg = st + OFF_AG;
        const float* pb = st + OFF_B;

        #pragma unroll
        for (int k8 = 0; k8 < 4; k8++) {
            const int kb = k8 * 8;

            uint32_t bf[4][2];
            #pragma unroll
            for (int nt = 0; nt < 4; nt++) {
                int n = wn + nt * 8 + row;
                bf[nt][0] = f2tf32(pb[(kb + col)     * B_STR + n]);
                bf[nt][1] = f2tf32(pb[(kb + col + 4) * B_STR + n]);
            }

            uint32_t af[2][4], gf[2][4];
            #pragma unroll
            for (int mt = 0; mt < 2; mt++) {
                int m = wm + mt * 16 + row;
                af[mt][0] = f2tf32(pa[(m)     * A_STR + kb + col]);
                af[mt][1] = f2tf32(pa[(m + 8) * A_STR + kb + col]);
                af[mt][2] = f2tf32(pa[(m)     * A_STR + kb + col + 4]);
                af[mt][3] = f2tf32(pa[(m + 8) * A_STR + kb + col + 4]);
                gf[mt][0] = f2tf32(pg[(m)     * A_STR + kb + col]);
                gf[mt][1] = f2tf32(pg[(m + 8) * A_STR + kb + col]);
                gf[mt][2] = f2tf32(pg[(m)     * A_STR + kb + col + 4]);
                gf[mt][3] = f2tf32(pg[(m + 8) * A_STR + kb + col + 4]);
            }

            #pragma unroll
            for (int mt = 0; mt < 2; mt++)
                #pragma unroll
                for (int nt = 0; nt < 4; nt++) {
                    mma_tf32(acc_a[mt][nt], af[mt], bf[nt]);
                    mma_tf32(acc_g[mt][nt], gf[mt], bf[nt]);
                }
        }
        __syncthreads();   // done reading this stage before it is re-filled
    }

    // ---- epilogue: bias + GLU, float2 stores ----
    #pragma unroll
    for (int mt = 0; mt < 2; mt++) {
        const int h_lo = h0 + wm + mt * 16 + row;       // c0,c1
        const int h_hi = h_lo + 8;                      // c2,c3
        const float ba0 = bias[h_lo],      bg0 = bias[h_lo + H_];
        const float ba1 = bias[h_hi],      bg1 = bias[h_hi + H_];
        #pragma unroll
        for (int nt = 0; nt < 4; nt++) {
            const int l = l0 + wn + nt * 8 + col * 2;
            float za, zg;
            float2 o2;

            za = acc_a[mt][nt][0] + ba0; zg = acc_g[mt][nt][0] + bg0;
            o2.x = za / (1.f + expf(-zg));
            za = acc_a[mt][nt][1] + ba0; zg = acc_g[mt][nt][1] + bg0;
            o2.y = za / (1.f + expf(-zg));
            *(float2*)&out[((size_t)b * H_ + h_lo) * L_ + l] = o2;

            za = acc_a[mt][nt][2] + ba1; zg = acc_g[mt][nt][2] + bg1;
            o2.x = za / (1.f + expf(-zg));
            za = acc_a[mt][nt][3] + ba1; zg = acc_g[mt][nt][3] + bg1;
            o2.y = za / (1.f + expf(-zg));
            *(float2*)&out[((size_t)b * H_ + h_hi) * L_ + l] = o2;
        }
    }
}

// ============================================================================
extern "C" void kernel_launch(void* const* d_in, const int* in_sizes, int n_in,
                              void* d_out, int out_size)
{
    const float* u    = (const float*)d_in[0];   // [B,H,L]
    const float* kern = (const float*)d_in[1];   // [1,H,128]
    const float* D    = (const float*)d_in[2];   // [1,H]
    const float* W    = (const float*)d_in[3];   // [2H,H]
    const float* bias = (const float*)d_in[4];   // [2H]
    float* out = (float*)d_out;                  // [B,H,L]

    conv_gelu_kernel<<<B_ * H_, 128>>>(u, kern, D);

    cudaFuncSetAttribute(gemm_glu_tc,
                         cudaFuncAttributeMaxDynamicSharedMemorySize, SMEM_BYTES);
    dim3 grid(L_ / 64, H_ / 128, B_);
    gemm_glu_tc<<<grid, 256, SMEM_BYTES>>>(W, bias, out);
}

// round 5
// speedup vs baseline: 2.4340x; 1.0301x over previous
#include <cuda_runtime.h>
#include <cstdint>
#include <math.h>

#define B_  2
#define H_  2048
#define L_  4096
#define LK  128
#define LAM 0.003f

// Scratch: gelu(conv(u)+D*u), tf32-pre-rounded, layout [B, H, L]
__device__ float g_y[(size_t)B_ * H_ * L_];
// tf32-pre-rounded copy of W [2H, H]
__device__ float g_wr[(size_t)2 * H_ * H_];

// ============================================================================
// Helpers
// ============================================================================
__device__ __forceinline__ uint32_t smem_to_u32(const void* p) {
    uint32_t a;
    asm("{ .reg .u64 t; cvta.to.shared.u64 t, %1; cvt.u32.u64 %0, t; }"
        : "=r"(a) : "l"(p));
    return a;
}
__device__ __forceinline__ float f2tf32f(float x) {
    uint32_t r;
    asm("cvt.rna.tf32.f32 %0, %1;" : "=r"(r) : "f"(x));
    return __uint_as_float(r);
}
__device__ __forceinline__ void cp16(uint32_t dst, const void* src) {
    asm volatile("cp.async.cg.shared.global [%0], [%1], 16;"
                 :: "r"(dst), "l"(src));
}
#define CP_COMMIT() asm volatile("cp.async.commit_group;" ::: "memory")
#define CP_WAIT(N)  asm volatile("cp.async.wait_group %0;" :: "n"(N) : "memory")

__device__ __forceinline__ void mma_tf32(float* c, const uint32_t* a, const uint32_t* b) {
    asm volatile(
        "mma.sync.aligned.m16n8k8.row.col.f32.tf32.tf32.f32 "
        "{%0,%1,%2,%3}, {%4,%5,%6,%7}, {%8,%9}, {%0,%1,%2,%3};"
        : "+f"(c[0]), "+f"(c[1]), "+f"(c[2]), "+f"(c[3])
        : "r"(a[0]), "r"(a[1]), "r"(a[2]), "r"(a[3]), "r"(b[0]), "r"(b[1]));
}

// ============================================================================
// Kernel 0: round W to tf32 precision once (out-of-loop cvt)
// ============================================================================
__global__ __launch_bounds__(256) void round_w_kernel(const float* __restrict__ W)
{
    size_t i = ((size_t)blockIdx.x * 256 + threadIdx.x) * 4;
    float4 v = *(const float4*)(W + i);
    v.x = f2tf32f(v.x); v.y = f2tf32f(v.y);
    v.z = f2tf32f(v.z); v.w = f2tf32f(v.w);
    *(float4*)(g_wr + i) = v;
}

// ============================================================================
// Kernel 1: 128-tap causal FIR conv + D skip + exact GELU, tf32-rounded out
// ============================================================================
__global__ __launch_bounds__(128) void conv_gelu_kernel(
    const float* __restrict__ u,
    const float* __restrict__ kern,
    const float* __restrict__ D)
{
    const int bh  = blockIdx.x;
    const int b   = bh / H_;
    const int h   = bh % H_;
    const int tid = threadIdx.x;

    __shared__ float ks[LK];
    __shared__ float us[1152];

    if (tid < LK) {
        float kv = kern[h * LK + tid];
        float a  = fabsf(kv) - LAM;
        a = a > 0.f ? a : 0.f;
        ks[tid] = (kv > 0.f) ? a : ((kv < 0.f) ? -a : 0.f);
    }
    const float Dh = D[h];
    const float* urow = u   + ((size_t)b * H_ + h) * L_;
    float*       yrow = g_y + ((size_t)b * H_ + h) * L_;

    for (int t = 0; t < 4; t++) {
        const int l0 = t * 1024;
        __syncthreads();
        for (int i = tid; i < 1152; i += 128) {
            int gl = l0 - 128 + i;
            us[i] = (gl >= 0) ? urow[gl] : 0.f;
        }
        __syncthreads();

        const int o = tid * 8;
        float uw[8];
        #pragma unroll
        for (int m = 0; m < 8; m++) uw[m] = us[o + 128 + m];

        float acc[8] = {0.f,0.f,0.f,0.f,0.f,0.f,0.f,0.f};

        #pragma unroll 8
        for (int j = 0; j < LK; j++) {
            const float kj = ks[j];
            #pragma unroll
            for (int m = 0; m < 8; m++) acc[m] = fmaf(kj, uw[m], acc[m]);
            #pragma unroll
            for (int m = 7; m > 0; m--) uw[m] = uw[m - 1];
            uw[0] = us[o + 127 - j];
        }

        #pragma unroll
        for (int m = 0; m < 8; m++) {
            float x  = acc[m] + Dh * us[o + 128 + m];
            float gv = 0.5f * x * (1.f + erff(x * 0.70710678118654752f));
            yrow[l0 + o + m] = f2tf32f(gv);
        }
    }
}

// ============================================================================
// Kernel 2: tf32 mma.sync GEMM + fused GLU.
// CTA: 128(h) x 64(l), both gates. BK=32 chunks, 3-stage cp.async pipeline.
// Operands are pre-rounded tf32 -> mainloop is pure LDS + MMA (no cvt).
// ============================================================================
#define BK       32
#define NKC      (H_ / BK)          // 64
#define A_STR    36
#define B_STR    72
#define OFF_AA   0
#define OFF_AG   (128 * A_STR)
#define OFF_B    (2 * 128 * A_STR)
#define STAGE_F  (2 * 128 * A_STR + 32 * B_STR)   // 11520 floats = 46080 B
#define NSTG     3
#define SMEM_BYTES (NSTG * STAGE_F * 4)           // 138240 B

__global__ __launch_bounds__(256, 1) void gemm_glu_tc(
    const float* __restrict__ bias,
    float* __restrict__ out)
{
    extern __shared__ float smem_f[];
    const uint32_t smem_u = smem_to_u32(smem_f);

    const int tid  = threadIdx.x;
    const int wid  = tid >> 5;
    const int lane = tid & 31;
    const int l0   = blockIdx.x * 64;
    const int h0   = blockIdx.y * 128;
    const int b    = blockIdx.z;

    const float* Y = g_y + (size_t)b * H_ * L_;
    const float* W = g_wr;

    const int ar = tid >> 3;
    const int ac = (tid & 7) * 4;
    const int br = tid >> 4;
    const int bc = (tid & 15) * 4;

    auto issue = [&](int k0, int s) {
        uint32_t sb = smem_u + (uint32_t)(s * STAGE_F) * 4u;
        #pragma unroll
        for (int i = 0; i < 4; i++) {
            int r = ar + i * 32;
            cp16(sb + (uint32_t)(OFF_AA + r * A_STR + ac) * 4u,
                 &W[(size_t)(h0 + r) * H_ + k0 + ac]);
            cp16(sb + (uint32_t)(OFF_AG + r * A_STR + ac) * 4u,
                 &W[(size_t)(h0 + r + H_) * H_ + k0 + ac]);
        }
        #pragma unroll
        for (int i = 0; i < 2; i++) {
            int r = br + i * 16;
            cp16(sb + (uint32_t)(OFF_B + r * B_STR + bc) * 4u,
                 &Y[(size_t)(k0 + r) * L_ + l0 + bc]);
        }
    };

    float acc_a[2][4][4];
    float acc_g[2][4][4];
    #pragma unroll
    for (int mt = 0; mt < 2; mt++)
        #pragma unroll
        for (int nt = 0; nt < 4; nt++)
            #pragma unroll
            for (int q = 0; q < 4; q++) { acc_a[mt][nt][q] = 0.f; acc_g[mt][nt][q] = 0.f; }

    const int wm = (wid & 3) * 32;
    const int wn = (wid >> 2) * 32;
    const int row = lane >> 2;
    const int col = lane & 3;

    issue(0, 0);        CP_COMMIT();
    issue(BK, 1);       CP_COMMIT();

    int s = 0;
    for (int kc = 0; kc < NKC; kc++) {
        if (kc + 2 < NKC) {
            issue((kc + 2) * BK, (kc + 2) % NSTG);
            CP_COMMIT();
            CP_WAIT(2);          // chunk kc resident
        } else if (kc + 1 < NKC) {
            CP_WAIT(1);
        } else {
            CP_WAIT(0);
        }
        __syncthreads();

        const uint32_t* st = (const uint32_t*)(smem_f + s * STAGE_F);
        const uint32_t* pa = st + OFF_AA;
        const uint32_t* pg = st + OFF_AG;
        const uint32_t* pb = st + OFF_B;

        #pragma unroll
        for (int k8 = 0; k8 < 4; k8++) {
            const int kb = k8 * 8;

            uint32_t bf[4][2];
            #pragma unroll
            for (int nt = 0; nt < 4; nt++) {
                int n = wn + nt * 8 + row;
                bf[nt][0] = pb[(kb + col)     * B_STR + n];
                bf[nt][1] = pb[(kb + col + 4) * B_STR + n];
            }

            uint32_t af[2][4], gf[2][4];
            #pragma unroll
            for (int mt = 0; mt < 2; mt++) {
                int m = wm + mt * 16 + row;
                af[mt][0] = pa[(m)     * A_STR + kb + col];
                af[mt][1] = pa[(m + 8) * A_STR + kb + col];
                af[mt][2] = pa[(m)     * A_STR + kb + col + 4];
                af[mt][3] = pa[(m + 8) * A_STR + kb + col + 4];
                gf[mt][0] = pg[(m)     * A_STR + kb + col];
                gf[mt][1] = pg[(m + 8) * A_STR + kb + col];
                gf[mt][2] = pg[(m)     * A_STR + kb + col + 4];
                gf[mt][3] = pg[(m + 8) * A_STR + kb + col + 4];
            }

            #pragma unroll
            for (int mt = 0; mt < 2; mt++)
                #pragma unroll
                for (int nt = 0; nt < 4; nt++) {
                    mma_tf32(acc_a[mt][nt], af[mt], bf[nt]);
                    mma_tf32(acc_g[mt][nt], gf[mt], bf[nt]);
                }
        }
        __syncthreads();
        s = (s + 1 == NSTG) ? 0 : s + 1;
    }

    // ---- epilogue: bias + GLU, float2 stores ----
    #pragma unroll
    for (int mt = 0; mt < 2; mt++) {
        const int h_lo = h0 + wm + mt * 16 + row;
        const int h_hi = h_lo + 8;
        const float ba0 = bias[h_lo],  bg0 = bias[h_lo + H_];
        const float ba1 = bias[h_hi],  bg1 = bias[h_hi + H_];
        #pragma unroll
        for (int nt = 0; nt < 4; nt++) {
            const int l = l0 + wn + nt * 8 + col * 2;
            float za, zg;
            float2 o2;

            za = acc_a[mt][nt][0] + ba0; zg = acc_g[mt][nt][0] + bg0;
            o2.x = za / (1.f + expf(-zg));
            za = acc_a[mt][nt][1] + ba0; zg = acc_g[mt][nt][1] + bg0;
            o2.y = za / (1.f + expf(-zg));
            *(float2*)&out[((size_t)b * H_ + h_lo) * L_ + l] = o2;

            za = acc_a[mt][nt][2] + ba1; zg = acc_g[mt][nt][2] + bg1;
            o2.x = za / (1.f + expf(-zg));
            za = acc_a[mt][nt][3] + ba1; zg = acc_g[mt][nt][3] + bg1;
            o2.y = za / (1.f + expf(-zg));
            *(float2*)&out[((size_t)b * H_ + h_hi) * L_ + l] = o2;
        }
    }
}

// ============================================================================
extern "C" void kernel_launch(void* const* d_in, const int* in_sizes, int n_in,
                              void* d_out, int out_size)
{
    const float* u    = (const float*)d_in[0];   // [B,H,L]
    const float* kern = (const float*)d_in[1];   // [1,H,128]
    const float* D    = (const float*)d_in[2];   // [1,H]
    const float* W    = (const float*)d_in[3];   // [2H,H]
    const float* bias = (const float*)d_in[4];   // [2H]
    float* out = (float*)d_out;                  // [B,H,L]

    round_w_kernel<<<(2 * H_ * H_) / (256 * 4), 256>>>(W);
    conv_gelu_kernel<<<B_ * H_, 128>>>(u, kern, D);

    cudaFuncSetAttribute(gemm_glu_tc,
                         cudaFuncAttributeMaxDynamicSharedMemorySize, SMEM_BYTES);
    dim3 grid(L_ / 64, H_ / 128, B_);
    gemm_glu_tc<<<grid, 256, SMEM_BYTES>>>(bias, out);
}

// round 6
// speedup vs baseline: 2.8730x; 1.1803x over previous
#include <cuda_runtime.h>
#include <cstdint>
#include <math.h>

#define B_  2
#define H_  2048
#define L_  4096
#define LK  128
#define LAM 0.003f

// Scratch: gelu(conv(u)+D*u), tf32-pre-rounded, layout [B, H, L]
__device__ float g_y[(size_t)B_ * H_ * L_];
// tf32-pre-rounded copy of W [2H, H]
__device__ float g_wr[(size_t)2 * H_ * H_];

// ============================================================================
// Helpers
// ============================================================================
__device__ __forceinline__ uint32_t smem_to_u32(const void* p) {
    uint32_t a;
    asm("{ .reg .u64 t; cvta.to.shared.u64 t, %1; cvt.u32.u64 %0, t; }"
        : "=r"(a) : "l"(p));
    return a;
}
__device__ __forceinline__ float f2tf32f(float x) {
    uint32_t r;
    asm("cvt.rna.tf32.f32 %0, %1;" : "=r"(r) : "f"(x));
    return __uint_as_float(r);
}
__device__ __forceinline__ void cp16(uint32_t dst, const void* src) {
    asm volatile("cp.async.cg.shared.global [%0], [%1], 16;"
                 :: "r"(dst), "l"(src));
}
#define CP_COMMIT() asm volatile("cp.async.commit_group;" ::: "memory")
#define CP_WAIT(N)  asm volatile("cp.async.wait_group %0;" :: "n"(N) : "memory")

__device__ __forceinline__ void mma_tf32(float* c, const uint32_t* a, const uint32_t* b) {
    asm volatile(
        "mma.sync.aligned.m16n8k8.row.col.f32.tf32.tf32.f32 "
        "{%0,%1,%2,%3}, {%4,%5,%6,%7}, {%8,%9}, {%0,%1,%2,%3};"
        : "+f"(c[0]), "+f"(c[1]), "+f"(c[2]), "+f"(c[3])
        : "r"(a[0]), "r"(a[1]), "r"(a[2]), "r"(a[3]), "r"(b[0]), "r"(b[1]));
}

// ============================================================================
// Kernel 0: round W to tf32 precision once
// ============================================================================
__global__ __launch_bounds__(256) void round_w_kernel(const float* __restrict__ W)
{
    size_t i = ((size_t)blockIdx.x * 256 + threadIdx.x) * 4;
    float4 v = *(const float4*)(W + i);
    v.x = f2tf32f(v.x); v.y = f2tf32f(v.y);
    v.z = f2tf32f(v.z); v.w = f2tf32f(v.w);
    *(float4*)(g_wr + i) = v;
}

// ============================================================================
// Kernel 1: 128-tap causal FIR conv + D skip + exact GELU, tf32-rounded out
// ============================================================================
__global__ __launch_bounds__(128) void conv_gelu_kernel(
    const float* __restrict__ u,
    const float* __restrict__ kern,
    const float* __restrict__ D)
{
    const int bh  = blockIdx.x;
    const int b   = bh / H_;
    const int h   = bh % H_;
    const int tid = threadIdx.x;

    __shared__ float ks[LK];
    __shared__ float us[1152];

    if (tid < LK) {
        float kv = kern[h * LK + tid];
        float a  = fabsf(kv) - LAM;
        a = a > 0.f ? a : 0.f;
        ks[tid] = (kv > 0.f) ? a : ((kv < 0.f) ? -a : 0.f);
    }
    const float Dh = D[h];
    const float* urow = u   + ((size_t)b * H_ + h) * L_;
    float*       yrow = g_y + ((size_t)b * H_ + h) * L_;

    for (int t = 0; t < 4; t++) {
        const int l0 = t * 1024;
        __syncthreads();
        for (int i = tid; i < 1152; i += 128) {
            int gl = l0 - 128 + i;
            us[i] = (gl >= 0) ? urow[gl] : 0.f;
        }
        __syncthreads();

        const int o = tid * 8;
        float uw[8];
        #pragma unroll
        for (int m = 0; m < 8; m++) uw[m] = us[o + 128 + m];

        float acc[8] = {0.f,0.f,0.f,0.f,0.f,0.f,0.f,0.f};

        #pragma unroll 8
        for (int j = 0; j < LK; j++) {
            const float kj = ks[j];
            #pragma unroll
            for (int m = 0; m < 8; m++) acc[m] = fmaf(kj, uw[m], acc[m]);
            #pragma unroll
            for (int m = 7; m > 0; m--) uw[m] = uw[m - 1];
            uw[0] = us[o + 127 - j];
        }

        #pragma unroll
        for (int m = 0; m < 8; m++) {
            float x  = acc[m] + Dh * us[o + 128 + m];
            float gv = 0.5f * x * (1.f + erff(x * 0.70710678118654752f));
            yrow[l0 + o + m] = f2tf32f(gv);
        }
    }
}

// ============================================================================
// Kernel 2: tf32 mma.sync GEMM + fused GLU.
// CTA: 128(h) x 128(l), both gates. 512 threads = 16 warps (4 per SMSP for
// latency hiding). Warp grid 4(M) x 4(N), warp tile 32x32 per gate.
// BK=32 chunks, 3-stage cp.async pipeline, pre-rounded tf32 operands.
// ============================================================================
#define BK       32
#define NKC      (H_ / BK)          // 64
#define BN       128
#define A_STR    36
#define B_STR    136
#define OFF_AA   0
#define OFF_AG   (128 * A_STR)                       // 4608
#define OFF_B    (2 * 128 * A_STR)                   // 9216
#define STAGE_F  (2 * 128 * A_STR + BK * B_STR)      // 13568 floats = 54272 B
#define NSTG     3
#define SMEM_BYTES (NSTG * STAGE_F * 4)              // 162816 B

__global__ __launch_bounds__(512, 1) void gemm_glu_tc(
    const float* __restrict__ bias,
    float* __restrict__ out)
{
    extern __shared__ float smem_f[];
    const uint32_t smem_u = smem_to_u32(smem_f);

    const int tid  = threadIdx.x;
    const int wid  = tid >> 5;
    const int lane = tid & 31;
    const int l0   = blockIdx.x * BN;
    const int h0   = blockIdx.y * 128;
    const int b    = blockIdx.z;

    const float* Y = g_y + (size_t)b * H_ * L_;
    const float* W = g_wr;

    // cp.async coordinates
    const int ar = tid >> 3;             // 0..63  (2 iters of +64)  A row
    const int ac = (tid & 7) * 4;        // 0..28               A col (k)
    const int brr = tid >> 5;            // 0..15  (2 iters of +16)  B row (k)
    const int bcc = (lane) * 4;          // 0..124              B col (n)

    auto issue = [&](int k0, int s) {
        uint32_t sb = smem_u + (uint32_t)(s * STAGE_F) * 4u;
        #pragma unroll
        for (int i = 0; i < 2; i++) {
            int r = ar + i * 64;
            cp16(sb + (uint32_t)(OFF_AA + r * A_STR + ac) * 4u,
                 &W[(size_t)(h0 + r) * H_ + k0 + ac]);
            cp16(sb + (uint32_t)(OFF_AG + r * A_STR + ac) * 4u,
                 &W[(size_t)(h0 + r + H_) * H_ + k0 + ac]);
        }
        #pragma unroll
        for (int i = 0; i < 2; i++) {
            int r = brr + i * 16;
            cp16(sb + (uint32_t)(OFF_B + r * B_STR + bcc) * 4u,
                 &Y[(size_t)(k0 + r) * L_ + l0 + bcc]);
        }
    };

    float acc_a[2][4][4];
    float acc_g[2][4][4];
    #pragma unroll
    for (int mt = 0; mt < 2; mt++)
        #pragma unroll
        for (int nt = 0; nt < 4; nt++)
            #pragma unroll
            for (int q = 0; q < 4; q++) { acc_a[mt][nt][q] = 0.f; acc_g[mt][nt][q] = 0.f; }

    const int wm  = (wid & 3) * 32;      // M offset within 128
    const int wn  = (wid >> 2) * 32;     // N offset within 128
    const int row = lane >> 2;           // 0..7
    const int col = lane & 3;            // 0..3

    issue(0, 0);        CP_COMMIT();
    issue(BK, 1);       CP_COMMIT();

    int s = 0;
    for (int kc = 0; kc < NKC; kc++) {
        if (kc + 2 < NKC) {
            issue((kc + 2) * BK, (kc + 2) % NSTG);
            CP_COMMIT();
            CP_WAIT(2);
        } else if (kc + 1 < NKC) {
            CP_WAIT(1);
        } else {
            CP_WAIT(0);
        }
        __syncthreads();

        const uint32_t* st = (const uint32_t*)(smem_f + s * STAGE_F);
        const uint32_t* pa = st + OFF_AA;
        const uint32_t* pg = st + OFF_AG;
        const uint32_t* pb = st + OFF_B;

        #pragma unroll
        for (int k8 = 0; k8 < 4; k8++) {
            const int kb = k8 * 8;

            uint32_t bf[4][2];
            #pragma unroll
            for (int nt = 0; nt < 4; nt++) {
                int n = wn + nt * 8 + row;
                bf[nt][0] = pb[(kb + col)     * B_STR + n];
                bf[nt][1] = pb[(kb + col + 4) * B_STR + n];
            }

            #pragma unroll
            for (int mt = 0; mt < 2; mt++) {
                const int m = wm + mt * 16 + row;
                uint32_t af[4], gf[4];
                af[0] = pa[(m)     * A_STR + kb + col];
                af[1] = pa[(m + 8) * A_STR + kb + col];
                af[2] = pa[(m)     * A_STR + kb + col + 4];
                af[3] = pa[(m + 8) * A_STR + kb + col + 4];
                gf[0] = pg[(m)     * A_STR + kb + col];
                gf[1] = pg[(m + 8) * A_STR + kb + col];
                gf[2] = pg[(m)     * A_STR + kb + col + 4];
                gf[3] = pg[(m + 8) * A_STR + kb + col + 4];
                #pragma unroll
                for (int nt = 0; nt < 4; nt++) {
                    mma_tf32(acc_a[mt][nt], af, bf[nt]);
                    mma_tf32(acc_g[mt][nt], gf, bf[nt]);
                }
            }
        }
        __syncthreads();
        s = (s + 1 == NSTG) ? 0 : s + 1;
    }

    // ---- epilogue: bias + GLU, float2 stores ----
    #pragma unroll
    for (int mt = 0; mt < 2; mt++) {
        const int h_lo = h0 + wm + mt * 16 + row;
        const int h_hi = h_lo + 8;
        const float ba0 = bias[h_lo],  bg0 = bias[h_lo + H_];
        const float ba1 = bias[h_hi],  bg1 = bias[h_hi + H_];
        #pragma unroll
        for (int nt = 0; nt < 4; nt++) {
            const int l = l0 + wn + nt * 8 + col * 2;
            float za, zg;
            float2 o2;

            za = acc_a[mt][nt][0] + ba0; zg = acc_g[mt][nt][0] + bg0;
            o2.x = za / (1.f + expf(-zg));
            za = acc_a[mt][nt][1] + ba0; zg = acc_g[mt][nt][1] + bg0;
            o2.y = za / (1.f + expf(-zg));
            *(float2*)&out[((size_t)b * H_ + h_lo) * L_ + l] = o2;

            za = acc_a[mt][nt][2] + ba1; zg = acc_g[mt][nt][2] + bg1;
            o2.x = za / (1.f + expf(-zg));
            za = acc_a[mt][nt][3] + ba1; zg = acc_g[mt][nt][3] + bg1;
            o2.y = za / (1.f + expf(-zg));
            *(float2*)&out[((size_t)b * H_ + h_hi) * L_ + l] = o2;
        }
    }
}

// ============================================================================
extern "C" void kernel_launch(void* const* d_in, const int* in_sizes, int n_in,
                              void* d_out, int out_size)
{
    const float* u    = (const float*)d_in[0];   // [B,H,L]
    const float* kern = (const float*)d_in[1];   // [1,H,128]
    const float* D    = (const float*)d_in[2];   // [1,H]
    const float* W    = (const float*)d_in[3];   // [2H,H]
    const float* bias = (const float*)d_in[4];   // [2H]
    float* out = (float*)d_out;                  // [B,H,L]

    round_w_kernel<<<(2 * H_ * H_) / (256 * 4), 256>>>(W);
    conv_gelu_kernel<<<B_ * H_, 128>>>(u, kern, D);

    cudaFuncSetAttribute(gemm_glu_tc,
                         cudaFuncAttributeMaxDynamicSharedMemorySize, SMEM_BYTES);
    dim3 grid(L_ / BN, H_ / 128, B_);
    gemm_glu_tc<<<grid, 512, SMEM_BYTES>>>(bias, out);
}

// round 7
// speedup vs baseline: 2.8923x; 1.0067x over previous
#include <cuda_runtime.h>
#include <cstdint>
#include <math.h>

#define B_  2
#define H_  2048
#define L_  4096
#define LK  128
#define LAM 0.003f

// Scratch: gelu(conv(u)+D*u), tf32-pre-rounded, layout [B, H, L]
__device__ float g_y[(size_t)B_ * H_ * L_];
// tf32-pre-rounded copy of W [2H, H]
__device__ float g_wr[(size_t)2 * H_ * H_];

// ============================================================================
// Helpers
// ============================================================================
__device__ __forceinline__ uint32_t smem_to_u32(const void* p) {
    uint32_t a;
    asm("{ .reg .u64 t; cvta.to.shared.u64 t, %1; cvt.u32.u64 %0, t; }"
        : "=r"(a) : "l"(p));
    return a;
}
__device__ __forceinline__ float f2tf32f(float x) {
    uint32_t r;
    asm("cvt.rna.tf32.f32 %0, %1;" : "=r"(r) : "f"(x));
    return __uint_as_float(r);
}
__device__ __forceinline__ void cp16(uint32_t dst, const void* src) {
    asm volatile("cp.async.cg.shared.global [%0], [%1], 16;"
                 :: "r"(dst), "l"(src));
}
#define CP_COMMIT() asm volatile("cp.async.commit_group;" ::: "memory")
#define CP_WAIT(N)  asm volatile("cp.async.wait_group %0;" :: "n"(N) : "memory")

__device__ __forceinline__ void mma_tf32(float* c, const uint32_t* a, const uint32_t* b) {
    asm volatile(
        "mma.sync.aligned.m16n8k8.row.col.f32.tf32.tf32.f32 "
        "{%0,%1,%2,%3}, {%4,%5,%6,%7}, {%8,%9}, {%0,%1,%2,%3};"
        : "+f"(c[0]), "+f"(c[1]), "+f"(c[2]), "+f"(c[3])
        : "r"(a[0]), "r"(a[1]), "r"(a[2]), "r"(a[3]), "r"(b[0]), "r"(b[1]));
}

// ============================================================================
// Kernel 0: round W to tf32 precision once
// ============================================================================
__global__ __launch_bounds__(256) void round_w_kernel(const float* __restrict__ W)
{
    size_t i = ((size_t)blockIdx.x * 256 + threadIdx.x) * 4;
    float4 v = *(const float4*)(W + i);
    v.x = f2tf32f(v.x); v.y = f2tf32f(v.y);
    v.z = f2tf32f(v.z); v.w = f2tf32f(v.w);
    *(float4*)(g_wr + i) = v;
}

// ============================================================================
// Kernel 1: 128-tap causal FIR conv + D skip + exact GELU, tf32-rounded out
// ============================================================================
__global__ __launch_bounds__(128) void conv_gelu_kernel(
    const float* __restrict__ u,
    const float* __restrict__ kern,
    const float* __restrict__ D)
{
    const int bh  = blockIdx.x;
    const int b   = bh / H_;
    const int h   = bh % H_;
    const int tid = threadIdx.x;

    __shared__ float ks[LK];
    __shared__ float us[1152];

    if (tid < LK) {
        float kv = kern[h * LK + tid];
        float a  = fabsf(kv) - LAM;
        a = a > 0.f ? a : 0.f;
        ks[tid] = (kv > 0.f) ? a : ((kv < 0.f) ? -a : 0.f);
    }
    const float Dh = D[h];
    const float* urow = u   + ((size_t)b * H_ + h) * L_;
    float*       yrow = g_y + ((size_t)b * H_ + h) * L_;

    for (int t = 0; t < 4; t++) {
        const int l0 = t * 1024;
        __syncthreads();
        for (int i = tid; i < 1152; i += 128) {
            int gl = l0 - 128 + i;
            us[i] = (gl >= 0) ? urow[gl] : 0.f;
        }
        __syncthreads();

        const int o = tid * 8;
        float uw[8];
        #pragma unroll
        for (int m = 0; m < 8; m++) uw[m] = us[o + 128 + m];

        float acc[8] = {0.f,0.f,0.f,0.f,0.f,0.f,0.f,0.f};

        #pragma unroll 8
        for (int j = 0; j < LK; j++) {
            const float kj = ks[j];
            #pragma unroll
            for (int m = 0; m < 8; m++) acc[m] = fmaf(kj, uw[m], acc[m]);
            #pragma unroll
            for (int m = 7; m > 0; m--) uw[m] = uw[m - 1];
            uw[0] = us[o + 127 - j];
        }

        #pragma unroll
        for (int m = 0; m < 8; m++) {
            float x  = acc[m] + Dh * us[o + 128 + m];
            float gv = 0.5f * x * (1.f + erff(x * 0.70710678118654752f));
            yrow[l0 + o + m] = f2tf32f(gv);
        }
    }
}

// ============================================================================
// Kernel 2: tf32 mma.sync GEMM + fused GLU.
// CTA: 128(h) x 128(l), both gates. 512 threads = 16 warps (4/SMSP).
// Warp grid 4(M) x 4(N); warp tile 32x32 per gate.
// BK=32, 4-stage cp.async pipeline, ONE __syncthreads per chunk:
//   CP_WAIT -> barrier -> issue(kc+3)  [overwrites stage (kc-1)%4, which the
//   barrier proves is fully consumed] -> compute(kc).
// ============================================================================
#define BK       32
#define NKC      (H_ / BK)          // 64
#define BN       128
#define A_STR    36
#define B_STR    136
#define OFF_AA   0
#define OFF_AG   (128 * A_STR)                       // 4608
#define OFF_B    (2 * 128 * A_STR)                   // 9216
#define STAGE_F  (2 * 128 * A_STR + BK * B_STR)      // 13568 floats = 54272 B
#define NSTG     4
#define SMEM_BYTES (NSTG * STAGE_F * 4)              // 217088 B

__global__ __launch_bounds__(512, 1) void gemm_glu_tc(
    const float* __restrict__ bias,
    float* __restrict__ out)
{
    extern __shared__ float smem_f[];
    const uint32_t smem_u = smem_to_u32(smem_f);

    const int tid  = threadIdx.x;
    const int wid  = tid >> 5;
    const int lane = tid & 31;
    const int l0   = blockIdx.x * BN;
    const int h0   = blockIdx.y * 128;
    const int b    = blockIdx.z;

    const float* Y = g_y + (size_t)b * H_ * L_;
    const float* W = g_wr;

    // cp.async coordinates
    const int ar  = tid >> 3;            // 0..63  (2 iters of +64)  A row
    const int ac  = (tid & 7) * 4;       // 0..28                    A col (k)
    const int brr = tid >> 5;            // 0..15  (2 iters of +16)  B row (k)
    const int bcc = lane * 4;            // 0..124                   B col (n)

    auto issue = [&](int k0, int s) {
        uint32_t sb = smem_u + (uint32_t)(s * STAGE_F) * 4u;
        #pragma unroll
        for (int i = 0; i < 2; i++) {
            int r = ar + i * 64;
            cp16(sb + (uint32_t)(OFF_AA + r * A_STR + ac) * 4u,
                 &W[(size_t)(h0 + r) * H_ + k0 + ac]);
            cp16(sb + (uint32_t)(OFF_AG + r * A_STR + ac) * 4u,
                 &W[(size_t)(h0 + r + H_) * H_ + k0 + ac]);
        }
        #pragma unroll
        for (int i = 0; i < 2; i++) {
            int r = brr + i * 16;
            cp16(sb + (uint32_t)(OFF_B + r * B_STR + bcc) * 4u,
                 &Y[(size_t)(k0 + r) * L_ + l0 + bcc]);
        }
    };

    float acc_a[2][4][4];
    float acc_g[2][4][4];
    #pragma unroll
    for (int mt = 0; mt < 2; mt++)
        #pragma unroll
        for (int nt = 0; nt < 4; nt++)
            #pragma unroll
            for (int q = 0; q < 4; q++) { acc_a[mt][nt][q] = 0.f; acc_g[mt][nt][q] = 0.f; }

    const int wm  = (wid & 3) * 32;
    const int wn  = (wid >> 2) * 32;
    const int row = lane >> 2;
    const int col = lane & 3;

    // prefill 3 stages
    issue(0,      0);  CP_COMMIT();
    issue(BK,     1);  CP_COMMIT();
    issue(2 * BK, 2);  CP_COMMIT();

    for (int kc = 0; kc < NKC; kc++) {
        if (kc <= NKC - 3)      { CP_WAIT(2); }
        else if (kc == NKC - 2) { CP_WAIT(1); }
        else                    { CP_WAIT(0); }
        __syncthreads();   // stage kc ready for all; stage kc-1 consumed by all

        if (kc + 3 < NKC) {
            issue((kc + 3) * BK, (kc + 3) & 3);   // overwrites stage (kc-1)&3
            CP_COMMIT();
        }

        const uint32_t* st = (const uint32_t*)(smem_f + (kc & 3) * STAGE_F);
        const uint32_t* pa = st + OFF_AA;
        const uint32_t* pg = st + OFF_AG;
        const uint32_t* pb = st + OFF_B;

        #pragma unroll
        for (int k8 = 0; k8 < 4; k8++) {
            const int kb = k8 * 8;

            uint32_t bf[4][2];
            #pragma unroll
            for (int nt = 0; nt < 4; nt++) {
                int n = wn + nt * 8 + row;
                bf[nt][0] = pb[(kb + col)     * B_STR + n];
                bf[nt][1] = pb[(kb + col + 4) * B_STR + n];
            }

            #pragma unroll
            for (int mt = 0; mt < 2; mt++) {
                const int m = wm + mt * 16 + row;
                uint32_t af[4], gf[4];
                af[0] = pa[(m)     * A_STR + kb + col];
                af[1] = pa[(m + 8) * A_STR + kb + col];
                af[2] = pa[(m)     * A_STR + kb + col + 4];
                af[3] = pa[(m + 8) * A_STR + kb + col + 4];
                gf[0] = pg[(m)     * A_STR + kb + col];
                gf[1] = pg[(m + 8) * A_STR + kb + col];
                gf[2] = pg[(m)     * A_STR + kb + col + 4];
                gf[3] = pg[(m + 8) * A_STR + kb + col + 4];
                #pragma unroll
                for (int nt = 0; nt < 4; nt++) {
                    mma_tf32(acc_a[mt][nt], af, bf[nt]);
                    mma_tf32(acc_g[mt][nt], gf, bf[nt]);
                }
            }
        }
        // no trailing barrier: next iteration's barrier protects stage reuse
    }

    // ---- epilogue: bias + GLU, float2 stores ----
    #pragma unroll
    for (int mt = 0; mt < 2; mt++) {
        const int h_lo = h0 + wm + mt * 16 + row;
        const int h_hi = h_lo + 8;
        const float ba0 = bias[h_lo],  bg0 = bias[h_lo + H_];
        const float ba1 = bias[h_hi],  bg1 = bias[h_hi + H_];
        #pragma unroll
        for (int nt = 0; nt < 4; nt++) {
            const int l = l0 + wn + nt * 8 + col * 2;
            float za, zg;
            float2 o2;

            za = acc_a[mt][nt][0] + ba0; zg = acc_g[mt][nt][0] + bg0;
            o2.x = za / (1.f + expf(-zg));
            za = acc_a[mt][nt][1] + ba0; zg = acc_g[mt][nt][1] + bg0;
            o2.y = za / (1.f + expf(-zg));
            *(float2*)&out[((size_t)b * H_ + h_lo) * L_ + l] = o2;

            za = acc_a[mt][nt][2] + ba1; zg = acc_g[mt][nt][2] + bg1;
            o2.x = za / (1.f + expf(-zg));
            za = acc_a[mt][nt][3] + ba1; zg = acc_g[mt][nt][3] + bg1;
            o2.y = za / (1.f + expf(-zg));
            *(float2*)&out[((size_t)b * H_ + h_hi) * L_ + l] = o2;
        }
    }
}

// ============================================================================
extern "C" void kernel_launch(void* const* d_in, const int* in_sizes, int n_in,
                              void* d_out, int out_size)
{
    const float* u    = (const float*)d_in[0];   // [B,H,L]
    const float* kern = (const float*)d_in[1];   // [1,H,128]
    const float* D    = (const float*)d_in[2];   // [1,H]
    const float* W    = (const float*)d_in[3];   // [2H,H]
    const float* bias = (const float*)d_in[4];   // [2H]
    float* out = (float*)d_out;                  // [B,H,L]

    round_w_kernel<<<(2 * H_ * H_) / (256 * 4), 256>>>(W);
    conv_gelu_kernel<<<B_ * H_, 128>>>(u, kern, D);

    cudaFuncSetAttribute(gemm_glu_tc,
                         cudaFuncAttributeMaxDynamicSharedMemorySize, SMEM_BYTES);
    dim3 grid(L_ / BN, H_ / 128, B_);
    gemm_glu_tc<<<grid, 512, SMEM_BYTES>>>(bias, out);
}

// round 8
// speedup vs baseline: 4.1985x; 1.4516x over previous
#include <cuda_runtime.h>
#include <cuda_fp16.h>
#include <cstdint>
#include <math.h>

#define B_  2
#define H_  2048
#define L_  4096
#define LK  128
#define LAM 0.003f

// Scratch: gelu(conv(u)+D*u) as fp16, layout [B, H, L]
__device__ __half g_y[(size_t)B_ * H_ * L_];
// fp16 copy of W [2H, H]
__device__ __half g_wh[(size_t)2 * H_ * H_];

// ============================================================================
// Helpers
// ============================================================================
__device__ __forceinline__ uint32_t smem_to_u32(const void* p) {
    uint32_t a;
    asm("{ .reg .u64 t; cvta.to.shared.u64 t, %1; cvt.u32.u64 %0, t; }"
        : "=r"(a) : "l"(p));
    return a;
}
__device__ __forceinline__ void cp16(uint32_t dst, const void* src) {
    asm volatile("cp.async.cg.shared.global [%0], [%1], 16;"
                 :: "r"(dst), "l"(src));
}
#define CP_COMMIT() asm volatile("cp.async.commit_group;" ::: "memory")
#define CP_WAIT(N)  asm volatile("cp.async.wait_group %0;" :: "n"(N) : "memory")

#define LDMATRIX_X4_TRANS(r0, r1, r2, r3, addr) \
    asm volatile("ldmatrix.sync.aligned.m8n8.x4.trans.shared.b16 {%0,%1,%2,%3}, [%4];" \
                 : "=r"(r0), "=r"(r1), "=r"(r2), "=r"(r3) : "r"(addr))

__device__ __forceinline__ void mma_f16(float* c, const uint32_t* a, const uint32_t* b) {
    asm volatile(
        "mma.sync.aligned.m16n8k16.row.col.f32.f16.f16.f32 "
        "{%0,%1,%2,%3}, {%4,%5,%6,%7}, {%8,%9}, {%0,%1,%2,%3};"
        : "+f"(c[0]), "+f"(c[1]), "+f"(c[2]), "+f"(c[3])
        : "r"(a[0]), "r"(a[1]), "r"(a[2]), "r"(a[3]), "r"(b[0]), "r"(b[1]));
}

// ============================================================================
// Kernel 0: convert W to fp16 once
// ============================================================================
__global__ __launch_bounds__(256) void conv_w_kernel(const float* __restrict__ W)
{
    size_t i = ((size_t)blockIdx.x * 256 + threadIdx.x) * 8;
    float4 v0 = *(const float4*)(W + i);
    float4 v1 = *(const float4*)(W + i + 4);
    __half2 h[4];
    h[0] = __floats2half2_rn(v0.x, v0.y);
    h[1] = __floats2half2_rn(v0.z, v0.w);
    h[2] = __floats2half2_rn(v1.x, v1.y);
    h[3] = __floats2half2_rn(v1.z, v1.w);
    *(uint4*)(g_wh + i) = *(const uint4*)h;
}

// ============================================================================
// Kernel 1: 128-tap causal FIR conv + D skip + exact GELU -> fp16 out
// ============================================================================
__global__ __launch_bounds__(128) void conv_gelu_kernel(
    const float* __restrict__ u,
    const float* __restrict__ kern,
    const float* __restrict__ D)
{
    const int bh  = blockIdx.x;
    const int b   = bh / H_;
    const int h   = bh % H_;
    const int tid = threadIdx.x;

    __shared__ float ks[LK];
    __shared__ float us[1152];

    if (tid < LK) {
        float kv = kern[h * LK + tid];
        float a  = fabsf(kv) - LAM;
        a = a > 0.f ? a : 0.f;
        ks[tid] = (kv > 0.f) ? a : ((kv < 0.f) ? -a : 0.f);
    }
    const float Dh = D[h];
    const float* urow = u   + ((size_t)b * H_ + h) * L_;
    __half*      yrow = g_y + ((size_t)b * H_ + h) * L_;

    for (int t = 0; t < 4; t++) {
        const int l0 = t * 1024;
        __syncthreads();
        for (int i = tid; i < 1152; i += 128) {
            int gl = l0 - 128 + i;
            us[i] = (gl >= 0) ? urow[gl] : 0.f;
        }
        __syncthreads();

        const int o = tid * 8;
        float uw[8];
        #pragma unroll
        for (int m = 0; m < 8; m++) uw[m] = us[o + 128 + m];

        float acc[8] = {0.f,0.f,0.f,0.f,0.f,0.f,0.f,0.f};

        #pragma unroll 8
        for (int j = 0; j < LK; j++) {
            const float kj = ks[j];
            #pragma unroll
            for (int m = 0; m < 8; m++) acc[m] = fmaf(kj, uw[m], acc[m]);
            #pragma unroll
            for (int m = 7; m > 0; m--) uw[m] = uw[m - 1];
            uw[0] = us[o + 127 - j];
        }

        #pragma unroll
        for (int m = 0; m < 8; m++) {
            float x  = acc[m] + Dh * us[o + 128 + m];
            float gv = 0.5f * x * (1.f + erff(x * 0.70710678118654752f));
            yrow[l0 + o + m] = __float2half_rn(gv);
        }
    }
}

// ============================================================================
// Kernel 2: fp16 mma.sync m16n8k16 GEMM + fused GLU.
// CTA: 128(h) x 128(l), both gates. 512 threads (4 warps/SMSP).
// Warp grid 4(M) x 4(N); warp tile 32x32 per gate.
// A frags: plain half2 LDS from [m][k] (stride 40 halves, conflict-free).
// B frags: ldmatrix.x4.trans from [k][n] (stride 136 halves, conflict-free).
// BK=32, 4-stage cp.async pipeline, one barrier per chunk.
// ============================================================================
#define BK       32
#define NKC      (H_ / BK)          // 64
#define BN       128
#define A_STRH   40                  // halves per A row
#define B_STRH   136                 // halves per B row
#define OFF_AA   0
#define OFF_AG   (128 * A_STRH)                      // 5120 halves
#define OFF_B    (2 * 128 * A_STRH)                  // 10240 halves
#define STAGE_H  (2 * 128 * A_STRH + BK * B_STRH)    // 14592 halves = 29184 B
#define NSTG     4
#define SMEM_BYTES (NSTG * STAGE_H * 2)              // 116736 B

__global__ __launch_bounds__(512, 1) void gemm_glu_tc(
    const float* __restrict__ bias,
    float* __restrict__ out)
{
    extern __shared__ __half smem_h[];
    const uint32_t smem_u = smem_to_u32(smem_h);

    const int tid  = threadIdx.x;
    const int wid  = tid >> 5;
    const int lane = tid & 31;
    const int l0   = blockIdx.x * BN;
    const int h0   = blockIdx.y * 128;
    const int b    = blockIdx.z;

    const __half* Y = g_y + (size_t)b * H_ * L_;
    const __half* W = g_wh;

    // cp.async coordinates (halves)
    const int a_row = tid >> 2;          // 0..127
    const int a_q   = (tid & 3) * 8;     // k offset 0,8,16,24
    const int b_row = tid >> 4;          // 0..31 (k)
    const int b_col = (tid & 15) * 8;    // n offset 0..120

    auto issue = [&](int k0, int s) {
        uint32_t sb = smem_u + (uint32_t)(s * STAGE_H) * 2u;
        cp16(sb + (uint32_t)(OFF_AA + a_row * A_STRH + a_q) * 2u,
             &W[(size_t)(h0 + a_row) * H_ + k0 + a_q]);
        cp16(sb + (uint32_t)(OFF_AG + a_row * A_STRH + a_q) * 2u,
             &W[(size_t)(h0 + a_row + H_) * H_ + k0 + a_q]);
        cp16(sb + (uint32_t)(OFF_B + b_row * B_STRH + b_col) * 2u,
             &Y[(size_t)(k0 + b_row) * L_ + l0 + b_col]);
    };

    float acc_a[2][4][4];
    float acc_g[2][4][4];
    #pragma unroll
    for (int mt = 0; mt < 2; mt++)
        #pragma unroll
        for (int nt = 0; nt < 4; nt++)
            #pragma unroll
            for (int q = 0; q < 4; q++) { acc_a[mt][nt][q] = 0.f; acc_g[mt][nt][q] = 0.f; }

    const int wm  = (wid & 3) * 32;
    const int wn  = (wid >> 2) * 32;
    const int g   = lane >> 2;           // group id 0..7
    const int t   = lane & 3;            // thread in group 0..3

    // ldmatrix lane address parts: lanes 0-7 tile0 (k rows 0-7), 8-15 tile1
    // (k rows 8-15), 16-23 tile2 (n+8, k 0-7), 24-31 tile3 (n+8, k 8-15)
    const int lm_k = (lane & 7) | (((lane >> 3) & 1) << 3);   // 0..15
    const int lm_n = (lane >> 4) << 3;                        // 0 or 8
    const uint32_t b_lane_off =
        (uint32_t)(OFF_B + lm_k * B_STRH + wn + lm_n) * 2u;

    // prefill 3 stages
    issue(0,      0);  CP_COMMIT();
    issue(BK,     1);  CP_COMMIT();
    issue(2 * BK, 2);  CP_COMMIT();

    for (int kc = 0; kc < NKC; kc++) {
        if (kc <= NKC - 3)      { CP_WAIT(2); }
        else if (kc == NKC - 2) { CP_WAIT(1); }
        else                    { CP_WAIT(0); }
        __syncthreads();

        if (kc + 3 < NKC) {
            issue((kc + 3) * BK, (kc + 3) & 3);
            CP_COMMIT();
        }

        const __half*  stg   = smem_h + (kc & 3) * STAGE_H;
        const uint32_t stg_u = smem_u + (uint32_t)((kc & 3) * STAGE_H) * 2u;
        const __half*  pa    = stg + OFF_AA;
        const __half*  pg    = stg + OFF_AG;

        #pragma unroll
        for (int ks = 0; ks < 2; ks++) {
            const int kb = ks * 16;

            uint32_t bb[4][2];
            LDMATRIX_X4_TRANS(bb[0][0], bb[0][1], bb[1][0], bb[1][1],
                              stg_u + b_lane_off + (uint32_t)(kb * B_STRH) * 2u);
            LDMATRIX_X4_TRANS(bb[2][0], bb[2][1], bb[3][0], bb[3][1],
                              stg_u + b_lane_off + (uint32_t)(kb * B_STRH + 16) * 2u);

            #pragma unroll
            for (int mt = 0; mt < 2; mt++) {
                const int m0 = wm + mt * 16 + g;
                const int kk = kb + 2 * t;
                uint32_t af[4], gf[4];
                af[0] = *(const uint32_t*)(pa + (m0)     * A_STRH + kk);
                af[1] = *(const uint32_t*)(pa + (m0 + 8) * A_STRH + kk);
                af[2] = *(const uint32_t*)(pa + (m0)     * A_STRH + kk + 8);
                af[3] = *(const uint32_t*)(pa + (m0 + 8) * A_STRH + kk + 8);
                gf[0] = *(const uint32_t*)(pg + (m0)     * A_STRH + kk);
                gf[1] = *(const uint32_t*)(pg + (m0 + 8) * A_STRH + kk);
                gf[2] = *(const uint32_t*)(pg + (m0)     * A_STRH + kk + 8);
                gf[3] = *(const uint32_t*)(pg + (m0 + 8) * A_STRH + kk + 8);
                #pragma unroll
                for (int nt = 0; nt < 4; nt++) {
                    mma_f16(acc_a[mt][nt], af, bb[nt]);
                    mma_f16(acc_g[mt][nt], gf, bb[nt]);
                }
            }
        }
        // next iteration's barrier protects stage reuse
    }

    // ---- epilogue: bias + GLU, float2 stores ----
    #pragma unroll
    for (int mt = 0; mt < 2; mt++) {
        const int h_lo = h0 + wm + mt * 16 + g;
        const int h_hi = h_lo + 8;
        const float ba0 = bias[h_lo],  bg0 = bias[h_lo + H_];
        const float ba1 = bias[h_hi],  bg1 = bias[h_hi + H_];
        #pragma unroll
        for (int nt = 0; nt < 4; nt++) {
            const int l = l0 + wn + nt * 8 + t * 2;
            float za, zg;
            float2 o2;

            za = acc_a[mt][nt][0] + ba0; zg = acc_g[mt][nt][0] + bg0;
            o2.x = za / (1.f + expf(-zg));
            za = acc_a[mt][nt][1] + ba0; zg = acc_g[mt][nt][1] + bg0;
            o2.y = za / (1.f + expf(-zg));
            *(float2*)&out[((size_t)b * H_ + h_lo) * L_ + l] = o2;

            za = acc_a[mt][nt][2] + ba1; zg = acc_g[mt][nt][2] + bg1;
            o2.x = za / (1.f + expf(-zg));
            za = acc_a[mt][nt][3] + ba1; zg = acc_g[mt][nt][3] + bg1;
            o2.y = za / (1.f + expf(-zg));
            *(float2*)&out[((size_t)b * H_ + h_hi) * L_ + l] = o2;
        }
    }
}

// ============================================================================
extern "C" void kernel_launch(void* const* d_in, const int* in_sizes, int n_in,
                              void* d_out, int out_size)
{
    const float* u    = (const float*)d_in[0];   // [B,H,L]
    const float* kern = (const float*)d_in[1];   // [1,H,128]
    const float* D    = (const float*)d_in[2];   // [1,H]
    const float* W    = (const float*)d_in[3];   // [2H,H]
    const float* bias = (const float*)d_in[4];   // [2H]
    float* out = (float*)d_out;                  // [B,H,L]

    conv_w_kernel<<<(2 * H_ * H_) / (256 * 8), 256>>>(W);
    conv_gelu_kernel<<<B_ * H_, 128>>>(u, kern, D);

    cudaFuncSetAttribute(gemm_glu_tc,
                         cudaFuncAttributeMaxDynamicSharedMemorySize, SMEM_BYTES);
    dim3 grid(L_ / BN, H_ / 128, B_);
    gemm_glu_tc<<<grid, 512, SMEM_BYTES>>>(bias, out);
}

// round 9
// speedup vs baseline: 4.4764x; 1.0662x over previous
#include <cuda_runtime.h>
#include <cuda_fp16.h>
#include <cstdint>
#include <math.h>

#define B_  2
#define H_  2048
#define L_  4096
#define LK  128
#define LAM 0.003f

// Scratch: gelu(conv(u)+D*u) as fp16, layout [B, H, L]
__device__ __half g_y[(size_t)B_ * H_ * L_];
// fp16 copy of W [2H, H]
__device__ __half g_wh[(size_t)2 * H_ * H_];

// ============================================================================
// Helpers
// ============================================================================
__device__ __forceinline__ uint32_t smem_to_u32(const void* p) {
    uint32_t a;
    asm("{ .reg .u64 t; cvta.to.shared.u64 t, %1; cvt.u32.u64 %0, t; }"
        : "=r"(a) : "l"(p));
    return a;
}
__device__ __forceinline__ void cp16(uint32_t dst, const void* src) {
    asm volatile("cp.async.cg.shared.global [%0], [%1], 16;"
                 :: "r"(dst), "l"(src));
}
#define CP_COMMIT() asm volatile("cp.async.commit_group;" ::: "memory")
#define CP_WAIT(N)  asm volatile("cp.async.wait_group %0;" :: "n"(N) : "memory")

#define LDMATRIX_X4(r0, r1, r2, r3, addr) \
    asm volatile("ldmatrix.sync.aligned.m8n8.x4.shared.b16 {%0,%1,%2,%3}, [%4];" \
                 : "=r"(r0), "=r"(r1), "=r"(r2), "=r"(r3) : "r"(addr))

#define LDMATRIX_X4_TRANS(r0, r1, r2, r3, addr) \
    asm volatile("ldmatrix.sync.aligned.m8n8.x4.trans.shared.b16 {%0,%1,%2,%3}, [%4];" \
                 : "=r"(r0), "=r"(r1), "=r"(r2), "=r"(r3) : "r"(addr))

__device__ __forceinline__ void mma_f16(float* c, const uint32_t* a, const uint32_t* b) {
    asm volatile(
        "mma.sync.aligned.m16n8k16.row.col.f32.f16.f16.f32 "
        "{%0,%1,%2,%3}, {%4,%5,%6,%7}, {%8,%9}, {%0,%1,%2,%3};"
        : "+f"(c[0]), "+f"(c[1]), "+f"(c[2]), "+f"(c[3])
        : "r"(a[0]), "r"(a[1]), "r"(a[2]), "r"(a[3]), "r"(b[0]), "r"(b[1]));
}

// ============================================================================
// Kernel 0: convert W to fp16 once
// ============================================================================
__global__ __launch_bounds__(256) void conv_w_kernel(const float* __restrict__ W)
{
    size_t i = ((size_t)blockIdx.x * 256 + threadIdx.x) * 8;
    float4 v0 = *(const float4*)(W + i);
    float4 v1 = *(const float4*)(W + i + 4);
    __half2 h[4];
    h[0] = __floats2half2_rn(v0.x, v0.y);
    h[1] = __floats2half2_rn(v0.z, v0.w);
    h[2] = __floats2half2_rn(v1.x, v1.y);
    h[3] = __floats2half2_rn(v1.z, v1.w);
    *(uint4*)(g_wh + i) = *(const uint4*)h;
}

// ============================================================================
// Kernel 1: 128-tap causal FIR conv + D skip + exact GELU -> fp16 out
// ============================================================================
__global__ __launch_bounds__(128) void conv_gelu_kernel(
    const float* __restrict__ u,
    const float* __restrict__ kern,
    const float* __restrict__ D)
{
    const int bh  = blockIdx.x;
    const int b   = bh / H_;
    const int h   = bh % H_;
    const int tid = threadIdx.x;

    __shared__ float ks[LK];
    __shared__ float us[1152];

    if (tid < LK) {
        float kv = kern[h * LK + tid];
        float a  = fabsf(kv) - LAM;
        a = a > 0.f ? a : 0.f;
        ks[tid] = (kv > 0.f) ? a : ((kv < 0.f) ? -a : 0.f);
    }
    const float Dh = D[h];
    const float* urow = u   + ((size_t)b * H_ + h) * L_;
    __half*      yrow = g_y + ((size_t)b * H_ + h) * L_;

    for (int t = 0; t < 4; t++) {
        const int l0 = t * 1024;
        __syncthreads();
        for (int i = tid; i < 1152; i += 128) {
            int gl = l0 - 128 + i;
            us[i] = (gl >= 0) ? urow[gl] : 0.f;
        }
        __syncthreads();

        const int o = tid * 8;
        float uw[8];
        #pragma unroll
        for (int m = 0; m < 8; m++) uw[m] = us[o + 128 + m];

        float acc[8] = {0.f,0.f,0.f,0.f,0.f,0.f,0.f,0.f};

        #pragma unroll 8
        for (int j = 0; j < LK; j++) {
            const float kj = ks[j];
            #pragma unroll
            for (int m = 0; m < 8; m++) acc[m] = fmaf(kj, uw[m], acc[m]);
            #pragma unroll
            for (int m = 7; m > 0; m--) uw[m] = uw[m - 1];
            uw[0] = us[o + 127 - j];
        }

        #pragma unroll
        for (int m = 0; m < 8; m++) {
            float x  = acc[m] + Dh * us[o + 128 + m];
            float gv = 0.5f * x * (1.f + erff(x * 0.70710678118654752f));
            yrow[l0 + o + m] = __float2half_rn(gv);
        }
    }
}

// ============================================================================
// Kernel 2: fp16 mma.sync m16n8k16 GEMM + fused GLU.
// CTA: 128(h) x 128(l), both gates. 512 threads (4 warps/SMSP).
// Warp grid 4(M) x 4(N); warp tile 32x32 per gate.
// A/G frags: ldmatrix.x4 (non-trans) from [m][k] (stride 40 halves).
// B frags:   ldmatrix.x4.trans  from [k][n] (stride 136 halves).
// BK=32, 4-stage cp.async pipeline, one barrier per chunk.
// ============================================================================
#define BK       32
#define NKC      (H_ / BK)          // 64
#define BN       128
#define A_STRH   40                  // halves per A row
#define B_STRH   136                 // halves per B row
#define OFF_AA   0
#define OFF_AG   (128 * A_STRH)                      // 5120 halves
#define OFF_B    (2 * 128 * A_STRH)                  // 10240 halves
#define STAGE_H  (2 * 128 * A_STRH + BK * B_STRH)    // 14592 halves = 29184 B
#define NSTG     4
#define SMEM_BYTES (NSTG * STAGE_H * 2)              // 116736 B

__global__ __launch_bounds__(512, 1) void gemm_glu_tc(
    const float* __restrict__ bias,
    float* __restrict__ out)
{
    extern __shared__ __half smem_h[];
    const uint32_t smem_u = smem_to_u32(smem_h);

    const int tid  = threadIdx.x;
    const int wid  = tid >> 5;
    const int lane = tid & 31;
    const int l0   = blockIdx.x * BN;
    const int h0   = blockIdx.y * 128;
    const int b    = blockIdx.z;

    const __half* Y = g_y + (size_t)b * H_ * L_;
    const __half* W = g_wh;

    // cp.async coordinates (halves)
    const int a_row = tid >> 2;          // 0..127
    const int a_q   = (tid & 3) * 8;     // k offset 0,8,16,24
    const int b_row = tid >> 4;          // 0..31 (k)
    const int b_col = (tid & 15) * 8;    // n offset 0..120

    auto issue = [&](int k0, int s) {
        uint32_t sb = smem_u + (uint32_t)(s * STAGE_H) * 2u;
        cp16(sb + (uint32_t)(OFF_AA + a_row * A_STRH + a_q) * 2u,
             &W[(size_t)(h0 + a_row) * H_ + k0 + a_q]);
        cp16(sb + (uint32_t)(OFF_AG + a_row * A_STRH + a_q) * 2u,
             &W[(size_t)(h0 + a_row + H_) * H_ + k0 + a_q]);
        cp16(sb + (uint32_t)(OFF_B + b_row * B_STRH + b_col) * 2u,
             &Y[(size_t)(k0 + b_row) * L_ + l0 + b_col]);
    };

    float acc_a[2][4][4];
    float acc_g[2][4][4];
    #pragma unroll
    for (int mt = 0; mt < 2; mt++)
        #pragma unroll
        for (int nt = 0; nt < 4; nt++)
            #pragma unroll
            for (int q = 0; q < 4; q++) { acc_a[mt][nt][q] = 0.f; acc_g[mt][nt][q] = 0.f; }

    const int wm  = (wid & 3) * 32;
    const int wn  = (wid >> 2) * 32;
    const int g   = lane >> 2;           // group id 0..7
    const int t   = lane & 3;            // thread in group 0..3

    // B ldmatrix lane address: tiles (k0-7,n0),(k8-15,n0),(k0-7,n8),(k8-15,n8)
    const int lm_k = (lane & 7) | (((lane >> 3) & 1) << 3);   // 0..15
    const int lm_n = (lane >> 4) << 3;                        // 0 or 8
    const uint32_t b_lane_off =
        (uint32_t)(OFF_B + lm_k * B_STRH + wn + lm_n) * 2u;

    // A ldmatrix lane address: row = m0 + (lane&15), k = kb + (lane>>4)*8
    // -> tiles in a0,a1,a2,a3 order for mma m16n8k16.
    const uint32_t a_lane_base =
        (uint32_t)((wm + (lane & 15)) * A_STRH + ((lane >> 4) << 3)) * 2u;

    // prefill 3 stages
    issue(0,      0);  CP_COMMIT();
    issue(BK,     1);  CP_COMMIT();
    issue(2 * BK, 2);  CP_COMMIT();

    for (int kc = 0; kc < NKC; kc++) {
        if (kc <= NKC - 3)      { CP_WAIT(2); }
        else if (kc == NKC - 2) { CP_WAIT(1); }
        else                    { CP_WAIT(0); }
        __syncthreads();

        if (kc + 3 < NKC) {
            issue((kc + 3) * BK, (kc + 3) & 3);
            CP_COMMIT();
        }

        const uint32_t stg_u = smem_u + (uint32_t)((kc & 3) * STAGE_H) * 2u;
        const uint32_t a_base = stg_u + (uint32_t)(OFF_AA * 2) + a_lane_base;
        const uint32_t g_base = stg_u + (uint32_t)(OFF_AG * 2) + a_lane_base;

        #pragma unroll
        for (int ks = 0; ks < 2; ks++) {
            const int kb = ks * 16;

            uint32_t bb[4][2];
            LDMATRIX_X4_TRANS(bb[0][0], bb[0][1], bb[1][0], bb[1][1],
                              stg_u + b_lane_off + (uint32_t)(kb * B_STRH) * 2u);
            LDMATRIX_X4_TRANS(bb[2][0], bb[2][1], bb[3][0], bb[3][1],
                              stg_u + b_lane_off + (uint32_t)(kb * B_STRH + 16) * 2u);

            #pragma unroll
            for (int mt = 0; mt < 2; mt++) {
                const uint32_t moff = (uint32_t)(mt * 16 * A_STRH + kb) * 2u;
                uint32_t af[4], gf[4];
                LDMATRIX_X4(af[0], af[1], af[2], af[3], a_base + moff);
                LDMATRIX_X4(gf[0], gf[1], gf[2], gf[3], g_base + moff);
                #pragma unroll
                for (int nt = 0; nt < 4; nt++) {
                    mma_f16(acc_a[mt][nt], af, bb[nt]);
                    mma_f16(acc_g[mt][nt], gf, bb[nt]);
                }
            }
        }
        // next iteration's barrier protects stage reuse
    }

    // ---- epilogue: bias + GLU, float2 stores ----
    #pragma unroll
    for (int mt = 0; mt < 2; mt++) {
        const int h_lo = h0 + wm + mt * 16 + g;
        const int h_hi = h_lo + 8;
        const float ba0 = bias[h_lo],  bg0 = bias[h_lo + H_];
        const float ba1 = bias[h_hi],  bg1 = bias[h_hi + H_];
        #pragma unroll
        for (int nt = 0; nt < 4; nt++) {
            const int l = l0 + wn + nt * 8 + t * 2;
            float za, zg;
            float2 o2;

            za = acc_a[mt][nt][0] + ba0; zg = acc_g[mt][nt][0] + bg0;
            o2.x = za / (1.f + expf(-zg));
            za = acc_a[mt][nt][1] + ba0; zg = acc_g[mt][nt][1] + bg0;
            o2.y = za / (1.f + expf(-zg));
            *(float2*)&out[((size_t)b * H_ + h_lo) * L_ + l] = o2;

            za = acc_a[mt][nt][2] + ba1; zg = acc_g[mt][nt][2] + bg1;
            o2.x = za / (1.f + expf(-zg));
            za = acc_a[mt][nt][3] + ba1; zg = acc_g[mt][nt][3] + bg1;
            o2.y = za / (1.f + expf(-zg));
            *(float2*)&out[((size_t)b * H_ + h_hi) * L_ + l] = o2;
        }
    }
}

// ============================================================================
extern "C" void kernel_launch(void* const* d_in, const int* in_sizes, int n_in,
                              void* d_out, int out_size)
{
    const float* u    = (const float*)d_in[0];   // [B,H,L]
    const float* kern = (const float*)d_in[1];   // [1,H,128]
    const float* D    = (const float*)d_in[2];   // [1,H]
    const float* W    = (const float*)d_in[3];   // [2H,H]
    const float* bias = (const float*)d_in[4];   // [2H]
    float* out = (float*)d_out;                  // [B,H,L]

    conv_w_kernel<<<(2 * H_ * H_) / (256 * 8), 256>>>(W);
    conv_gelu_kernel<<<B_ * H_, 128>>>(u, kern, D);

    cudaFuncSetAttribute(gemm_glu_tc,
                         cudaFuncAttributeMaxDynamicSharedMemorySize, SMEM_BYTES);
    dim3 grid(L_ / BN, H_ / 128, B_);
    gemm_glu_tc<<<grid, 512, SMEM_BYTES>>>(bias, out);
}

// round 10
// speedup vs baseline: 6.3853x; 1.4264x over previous
#include <cuda_runtime.h>
#include <cuda_fp16.h>
#include <cstdint>
#include <math.h>

#define B_  2
#define H_  2048
#define L_  4096
#define LK  128
#define LAM 0.003f

// Scratch: gelu(conv(u)+D*u) as fp16, layout [B, H, L]
__device__ __half g_y[(size_t)B_ * H_ * L_];
// fp16 copy of W [2H, H]
__device__ __half g_wh[(size_t)2 * H_ * H_];

// ============================================================================
// Helpers
// ============================================================================
__device__ __forceinline__ uint32_t smem_to_u32(const void* p) {
    uint32_t a;
    asm("{ .reg .u64 t; cvta.to.shared.u64 t, %1; cvt.u32.u64 %0, t; }"
        : "=r"(a) : "l"(p));
    return a;
}
__device__ __forceinline__ void cp16(uint32_t dst, const void* src) {
    asm volatile("cp.async.cg.shared.global [%0], [%1], 16;"
                 :: "r"(dst), "l"(src));
}
#define CP_COMMIT() asm volatile("cp.async.commit_group;" ::: "memory")
#define CP_WAIT(N)  asm volatile("cp.async.wait_group %0;" :: "n"(N) : "memory")

#define LDMATRIX_X2(r0, r1, addr) \
    asm volatile("ldmatrix.sync.aligned.m8n8.x2.shared.b16 {%0,%1}, [%2];" \
                 : "=r"(r0), "=r"(r1) : "r"(addr))

#define LDMATRIX_X4(r0, r1, r2, r3, addr) \
    asm volatile("ldmatrix.sync.aligned.m8n8.x4.shared.b16 {%0,%1,%2,%3}, [%4];" \
                 : "=r"(r0), "=r"(r1), "=r"(r2), "=r"(r3) : "r"(addr))

#define LDMATRIX_X4_TRANS(r0, r1, r2, r3, addr) \
    asm volatile("ldmatrix.sync.aligned.m8n8.x4.trans.shared.b16 {%0,%1,%2,%3}, [%4];" \
                 : "=r"(r0), "=r"(r1), "=r"(r2), "=r"(r3) : "r"(addr))

__device__ __forceinline__ void mma_f16(float* c, const uint32_t* a, const uint32_t* b) {
    asm volatile(
        "mma.sync.aligned.m16n8k16.row.col.f32.f16.f16.f32 "
        "{%0,%1,%2,%3}, {%4,%5,%6,%7}, {%8,%9}, {%0,%1,%2,%3};"
        : "+f"(c[0]), "+f"(c[1]), "+f"(c[2]), "+f"(c[3])
        : "r"(a[0]), "r"(a[1]), "r"(a[2]), "r"(a[3]), "r"(b[0]), "r"(b[1]));
}

// ============================================================================
// Kernel 0: convert W to fp16 once
// ============================================================================
__global__ __launch_bounds__(256) void conv_w_kernel(const float* __restrict__ W)
{
    size_t i = ((size_t)blockIdx.x * 256 + threadIdx.x) * 8;
    float4 v0 = *(const float4*)(W + i);
    float4 v1 = *(const float4*)(W + i + 4);
    __half2 h[4];
    h[0] = __floats2half2_rn(v0.x, v0.y);
    h[1] = __floats2half2_rn(v0.z, v0.w);
    h[2] = __floats2half2_rn(v1.x, v1.y);
    h[3] = __floats2half2_rn(v1.z, v1.w);
    *(uint4*)(g_wh + i) = *(const uint4*)h;
}

// ============================================================================
// Kernel 1: 128-tap causal FIR conv via fp16 tensor cores (kernel-Toeplitz)
// + fp32 D skip + exact GELU -> fp16 out.
// One CTA per (b,h) row, 128 threads = 4 warps, each warp 64 n-columns.
// y[16n+i] = sum_s A_s[i][t] * B_s[t][n],  A_s[i][t] = k[i-t+16s],
// B_s[t][n] = u[16(n-s)+t]  (contiguous fp16 u segments; ldmatrix.x2 view).
// ============================================================================
__global__ __launch_bounds__(128) void conv_gelu_mma(
    const float* __restrict__ u,
    const float* __restrict__ kern,
    const float* __restrict__ D)
{
    __shared__ __half uh[4224];          // u row: halo 128 + 4096
    __shared__ __half At[9][16][24];     // Toeplitz tiles, row stride 24
    __shared__ float  ks[LK];
    __shared__ float  buf[4][16][10];    // per-warp C staging

    const int bh   = blockIdx.x;
    const int b    = bh / H_;
    const int h    = bh % H_;
    const int tid  = threadIdx.x;
    const int wid  = tid >> 5;
    const int lane = tid & 31;

    const float* urow = u   + ((size_t)b * H_ + h) * L_;
    __half*      yrow = g_y + ((size_t)b * H_ + h) * L_;

    // soft-thresholded kernel (fp32)
    {
        float kv = kern[h * LK + tid & 0x7fffffff];  // tid<128 always
        kv = kern[h * LK + tid];
        float a  = fabsf(kv) - LAM;
        a = a > 0.f ? a : 0.f;
        ks[tid] = (kv > 0.f) ? a : ((kv < 0.f) ? -a : 0.f);
    }
    // u row -> fp16 with left halo of zeros
    for (int idx = tid; idx < 4224; idx += 128) {
        int l = idx - 128;
        uh[idx] = (l >= 0) ? __float2half_rn(urow[l]) : __float2half_rn(0.f);
    }
    __syncthreads();
    // Toeplitz tiles: At[s][i][t] = k[i - t + 16 s] (0 outside [0,128))
    for (int e = tid; e < 9 * 256; e += 128) {
        int s = e >> 8, rr = e & 255, i = rr >> 4, t = rr & 15;
        int d = i - t + 16 * s;
        At[s][i][t] = (d >= 0 && d < LK) ? __float2half_rn(ks[d])
                                         : __float2half_rn(0.f);
    }
    __syncthreads();

    // A fragments (hoisted: independent of n)
    const int r = lane >> 2;     // group id 0..7
    const int c = lane & 3;      // thread in group
    uint32_t af[9][4];
    #pragma unroll
    for (int s = 0; s < 9; s++) {
        af[s][0] = *(const uint32_t*)&At[s][r][2 * c];
        af[s][1] = *(const uint32_t*)&At[s][r + 8][2 * c];
        af[s][2] = *(const uint32_t*)&At[s][r][2 * c + 8];
        af[s][3] = *(const uint32_t*)&At[s][r + 8][2 * c + 8];
    }

    // ldmatrix.x2 lane offset into a B tile ([n][k] rows of 16 halves):
    // lanes 0-7 -> rows n (k 0-7), lanes 8-15 -> rows n (k 8-15)
    const uint32_t uh_u32 = smem_to_u32(uh);
    const int lm = (lane < 8) ? 16 * lane
                 : (lane < 16 ? 16 * (lane - 8) + 8 : 0);

    const float Dh = D[h];
    float (*bw)[10] = buf[wid];

    #pragma unroll 1
    for (int nt = 0; nt < 8; nt++) {
        const int n0 = wid * 64 + nt * 8;
        float cc[4] = {0.f, 0.f, 0.f, 0.f};

        #pragma unroll
        for (int s = 0; s < 9; s++) {
            const int base = 128 + 16 * (n0 - s);
            uint32_t bb[2];
            LDMATRIX_X2(bb[0], bb[1], uh_u32 + (uint32_t)(base + lm) * 2u);
            mma_f16(cc, af[s], bb);
        }

        // stage C tile: cc0,cc1 -> rows r, cols 2c,2c+1; cc2,cc3 -> row r+8
        bw[r][2 * c]         = cc[0];
        bw[r][2 * c + 1]     = cc[1];
        bw[r + 8][2 * c]     = cc[2];
        bw[r + 8][2 * c + 1] = cc[3];
        __syncwarp();

        // epilogue: 128 outputs l = 16*n0 .. +127; lane handles 4 consecutive
        const int lbase = 16 * n0 + 4 * lane;
        float4 uv = *(const float4*)&urow[lbase];
        const float us4[4] = {uv.x, uv.y, uv.z, uv.w};
        __half hv[4];
        #pragma unroll
        for (int j = 0; j < 4; j++) {
            int li = 4 * lane + j;
            float x = bw[li & 15][li >> 4] + Dh * us4[j];
            float gv = 0.5f * x * (1.f + erff(x * 0.70710678118654752f));
            hv[j] = __float2half_rn(gv);
        }
        *(uint2*)&yrow[lbase] = *(const uint2*)hv;
        __syncwarp();
    }
}

// ============================================================================
// Kernel 2: fp16 mma.sync m16n8k16 GEMM + fused GLU (unchanged from R9).
// ============================================================================
#define BK       32
#define NKC      (H_ / BK)          // 64
#define BN       128
#define A_STRH   40
#define B_STRH   136
#define OFF_AA   0
#define OFF_AG   (128 * A_STRH)
#define OFF_B    (2 * 128 * A_STRH)
#define STAGE_H  (2 * 128 * A_STRH + BK * B_STRH)
#define NSTG     4
#define SMEM_BYTES (NSTG * STAGE_H * 2)

__global__ __launch_bounds__(512, 1) void gemm_glu_tc(
    const float* __restrict__ bias,
    float* __restrict__ out)
{
    extern __shared__ __half smem_h[];
    const uint32_t smem_u = smem_to_u32(smem_h);

    const int tid  = threadIdx.x;
    const int wid  = tid >> 5;
    const int lane = tid & 31;
    const int l0   = blockIdx.x * BN;
    const int h0   = blockIdx.y * 128;
    const int b    = blockIdx.z;

    const __half* Y = g_y + (size_t)b * H_ * L_;
    const __half* W = g_wh;

    const int a_row = tid >> 2;
    const int a_q   = (tid & 3) * 8;
    const int b_row = tid >> 4;
    const int b_col = (tid & 15) * 8;

    auto issue = [&](int k0, int s) {
        uint32_t sb = smem_u + (uint32_t)(s * STAGE_H) * 2u;
        cp16(sb + (uint32_t)(OFF_AA + a_row * A_STRH + a_q) * 2u,
             &W[(size_t)(h0 + a_row) * H_ + k0 + a_q]);
        cp16(sb + (uint32_t)(OFF_AG + a_row * A_STRH + a_q) * 2u,
             &W[(size_t)(h0 + a_row + H_) * H_ + k0 + a_q]);
        cp16(sb + (uint32_t)(OFF_B + b_row * B_STRH + b_col) * 2u,
             &Y[(size_t)(k0 + b_row) * L_ + l0 + b_col]);
    };

    float acc_a[2][4][4];
    float acc_g[2][4][4];
    #pragma unroll
    for (int mt = 0; mt < 2; mt++)
        #pragma unroll
        for (int nt = 0; nt < 4; nt++)
            #pragma unroll
            for (int q = 0; q < 4; q++) { acc_a[mt][nt][q] = 0.f; acc_g[mt][nt][q] = 0.f; }

    const int wm  = (wid & 3) * 32;
    const int wn  = (wid >> 2) * 32;
    const int g   = lane >> 2;
    const int t   = lane & 3;

    const int lm_k = (lane & 7) | (((lane >> 3) & 1) << 3);
    const int lm_n = (lane >> 4) << 3;
    const uint32_t b_lane_off =
        (uint32_t)(OFF_B + lm_k * B_STRH + wn + lm_n) * 2u;

    const uint32_t a_lane_base =
        (uint32_t)((wm + (lane & 15)) * A_STRH + ((lane >> 4) << 3)) * 2u;

    issue(0,      0);  CP_COMMIT();
    issue(BK,     1);  CP_COMMIT();
    issue(2 * BK, 2);  CP_COMMIT();

    for (int kc = 0; kc < NKC; kc++) {
        if (kc <= NKC - 3)      { CP_WAIT(2); }
        else if (kc == NKC - 2) { CP_WAIT(1); }
        else                    { CP_WAIT(0); }
        __syncthreads();

        if (kc + 3 < NKC) {
            issue((kc + 3) * BK, (kc + 3) & 3);
            CP_COMMIT();
        }

        const uint32_t stg_u = smem_u + (uint32_t)((kc & 3) * STAGE_H) * 2u;
        const uint32_t a_base = stg_u + (uint32_t)(OFF_AA * 2) + a_lane_base;
        const uint32_t g_base = stg_u + (uint32_t)(OFF_AG * 2) + a_lane_base;

        #pragma unroll
        for (int ks = 0; ks < 2; ks++) {
            const int kb = ks * 16;

            uint32_t bb[4][2];
            LDMATRIX_X4_TRANS(bb[0][0], bb[0][1], bb[1][0], bb[1][1],
                              stg_u + b_lane_off + (uint32_t)(kb * B_STRH) * 2u);
            LDMATRIX_X4_TRANS(bb[2][0], bb[2][1], bb[3][0], bb[3][1],
                              stg_u + b_lane_off + (uint32_t)(kb * B_STRH + 16) * 2u);

            #pragma unroll
            for (int mt = 0; mt < 2; mt++) {
                const uint32_t moff = (uint32_t)(mt * 16 * A_STRH + kb) * 2u;
                uint32_t af[4], gf[4];
                LDMATRIX_X4(af[0], af[1], af[2], af[3], a_base + moff);
                LDMATRIX_X4(gf[0], gf[1], gf[2], gf[3], g_base + moff);
                #pragma unroll
                for (int nt = 0; nt < 4; nt++) {
                    mma_f16(acc_a[mt][nt], af, bb[nt]);
                    mma_f16(acc_g[mt][nt], gf, bb[nt]);
                }
            }
        }
    }

    #pragma unroll
    for (int mt = 0; mt < 2; mt++) {
        const int h_lo = h0 + wm + mt * 16 + g;
        const int h_hi = h_lo + 8;
        const float ba0 = bias[h_lo],  bg0 = bias[h_lo + H_];
        const float ba1 = bias[h_hi],  bg1 = bias[h_hi + H_];
        #pragma unroll
        for (int nt = 0; nt < 4; nt++) {
            const int l = l0 + wn + nt * 8 + t * 2;
            float za, zg;
            float2 o2;

            za = acc_a[mt][nt][0] + ba0; zg = acc_g[mt][nt][0] + bg0;
            o2.x = za / (1.f + expf(-zg));
            za = acc_a[mt][nt][1] + ba0; zg = acc_g[mt][nt][1] + bg0;
            o2.y = za / (1.f + expf(-zg));
            *(float2*)&out[((size_t)b * H_ + h_lo) * L_ + l] = o2;

            za = acc_a[mt][nt][2] + ba1; zg = acc_g[mt][nt][2] + bg1;
            o2.x = za / (1.f + expf(-zg));
            za = acc_a[mt][nt][3] + ba1; zg = acc_g[mt][nt][3] + bg1;
            o2.y = za / (1.f + expf(-zg));
            *(float2*)&out[((size_t)b * H_ + h_hi) * L_ + l] = o2;
        }
    }
}

// ============================================================================
extern "C" void kernel_launch(void* const* d_in, const int* in_sizes, int n_in,
                              void* d_out, int out_size)
{
    const float* u    = (const float*)d_in[0];   // [B,H,L]
    const float* kern = (const float*)d_in[1];   // [1,H,128]
    const float* D    = (const float*)d_in[2];   // [1,H]
    const float* W    = (const float*)d_in[3];   // [2H,H]
    const float* bias = (const float*)d_in[4];   // [2H]
    float* out = (float*)d_out;                  // [B,H,L]

    conv_w_kernel<<<(2 * H_ * H_) / (256 * 8), 256>>>(W);
    conv_gelu_mma<<<B_ * H_, 128>>>(u, kern, D);

    cudaFuncSetAttribute(gemm_glu_tc,
                         cudaFuncAttributeMaxDynamicSharedMemorySize, SMEM_BYTES);
    dim3 grid(L_ / BN, H_ / 128, B_);
    gemm_glu_tc<<<grid, 512, SMEM_BYTES>>>(bias, out);
}